// round 3
// baseline (speedup 1.0000x reference)
#include <cuda_runtime.h>
#include <math.h>

#define P    8192
#define D    128
#define NU   8234
#define NHE  51
#define NUC  42
#define CW   768
#define MPAD 8320
#define NT   65

// ---------------- device scratch ----------------
__device__ float g_A[P*D];
__device__ float g_B[P*D];
__device__ float g_C2[P*D];
__device__ float g_acc[P*D];
__device__ float g_hg[P*D];
__device__ float g_z2a[P*D];
__device__ float g_uA[NU*D];
__device__ float g_uB[NU*D];
__device__ float g_uC[NU*D];
__device__ float g_uacc[NU*D];
__device__ float g_ue[NU*D];
__device__ float g_z2b[NU*D];
__device__ float g_hus[NHE*D];
__device__ float g_ucl[NUC*D];
__device__ float g_X1r[P*D], g_X1i[P*D], g_X2r[P*D], g_X2i[P*D];
__device__ float g_Tr[(size_t)P*CW], g_Ti[(size_t)P*CW];
__device__ float g_Gr[P*D], g_Gi[P*D];
__device__ float g_fr[P*D], g_fi[P*D];
__device__ float g_fp[P*D];
__device__ float g_part[(size_t)8*MPAD*128];
__device__ float g_rp[(size_t)NT*MPAD];
__device__ float g_cp[(size_t)NT*MPAD];
__device__ float g_lr[NU], g_lc[NU], g_dg[NU];
__device__ float g_psum[8*NU];
__device__ float g_tabc[D*D], g_tabs[D*D];
__device__ float g_CrP[CW*D], g_CiP[CW*D];
__device__ float g_br[D], g_bi[D];
__device__ float g_fu[D];
__device__ float g_loss;

// ---------------- TF32 MMA primitives ----------------
__device__ __forceinline__ unsigned f2t(float x) {
    unsigned u;
    asm("cvt.rna.tf32.f32 %0, %1;" : "=r"(u) : "f"(x));
    return u;
}
__device__ __forceinline__ void mma8(float* c, const unsigned* a, const unsigned* b) {
    asm volatile(
        "mma.sync.aligned.m16n8k8.row.col.f32.tf32.tf32.f32 "
        "{%0,%1,%2,%3},{%4,%5,%6,%7},{%8,%9},{%0,%1,%2,%3};"
        : "+f"(c[0]), "+f"(c[1]), "+f"(c[2]), "+f"(c[3])
        : "r"(a[0]), "r"(a[1]), "r"(a[2]), "r"(a[3]), "r"(b[0]), "r"(b[1]));
}

// =====================================================================
// Fused InfoNCE via compensated-TF32 MMA: sim = 5 * Z1 @ Z2^T (K=128),
// e = exp(sim - 5) in epilogue, per-tile row/col partial sums only.
// grid (nt, nt), 256 threads = 8 warps (2 x 4), warp tile 64x32.
// =====================================================================
__global__ __launch_bounds__(256)
void nce_mma_k(const float* __restrict__ Z1, const float* __restrict__ Z2,
               int M, float* __restrict__ rowp, float* __restrict__ colp)
{
    __shared__ __align__(16) float As[128][36];
    __shared__ __align__(16) float Bs[128][36];
    __shared__ float redR[128][4];
    __shared__ float redC[128][2];

    int t = threadIdx.x, lane = t & 31, w = t >> 5;
    int wr = w >> 2, wc = w & 3;
    int bm = blockIdx.y * 128, bn = blockIdx.x * 128;

    float Cacc[16][4];
    #pragma unroll
    for (int f = 0; f < 16; f++)
        #pragma unroll
        for (int q = 0; q < 4; q++) Cacc[f][q] = 0.f;

    #pragma unroll 1
    for (int kc = 0; kc < 128; kc += 32) {
        #pragma unroll
        for (int i = 0; i < 4; i++) {
            int idx = t + i * 256;
            int row = idx >> 3, c4 = (idx & 7) * 4;
            int gm = bm + row;
            float4 v = (gm < M) ? *(const float4*)&Z1[(size_t)gm * 128 + kc + c4]
                                : make_float4(0.f, 0.f, 0.f, 0.f);
            *(float4*)&As[row][c4] = v;
        }
        #pragma unroll
        for (int i = 0; i < 4; i++) {
            int idx = t + i * 256;
            int row = idx >> 3, c4 = (idx & 7) * 4;
            int gn = bn + row;
            float4 v = (gn < M) ? *(const float4*)&Z2[(size_t)gn * 128 + kc + c4]
                                : make_float4(0.f, 0.f, 0.f, 0.f);
            *(float4*)&Bs[row][c4] = v;
        }
        __syncthreads();
        #pragma unroll
        for (int k8 = 0; k8 < 32; k8 += 8) {
            unsigned Ah[4][4], Al[4][4];
            int mrow = lane >> 2, kk = k8 + (lane & 3);
            #pragma unroll
            for (int mi = 0; mi < 4; mi++) {
                int m0 = wr * 64 + mi * 16 + mrow;
                float a0 = As[m0][kk],     a1 = As[m0 + 8][kk];
                float a2 = As[m0][kk + 4], a3 = As[m0 + 8][kk + 4];
                Ah[mi][0] = f2t(a0); Al[mi][0] = f2t(a0 - __uint_as_float(Ah[mi][0]));
                Ah[mi][1] = f2t(a1); Al[mi][1] = f2t(a1 - __uint_as_float(Ah[mi][1]));
                Ah[mi][2] = f2t(a2); Al[mi][2] = f2t(a2 - __uint_as_float(Ah[mi][2]));
                Ah[mi][3] = f2t(a3); Al[mi][3] = f2t(a3 - __uint_as_float(Ah[mi][3]));
            }
            #pragma unroll
            for (int ni = 0; ni < 4; ni++) {
                int n0 = wc * 32 + ni * 8 + mrow;
                float b0 = Bs[n0][kk], b1 = Bs[n0][kk + 4];
                unsigned bh[2], bl[2];
                bh[0] = f2t(b0); bl[0] = f2t(b0 - __uint_as_float(bh[0]));
                bh[1] = f2t(b1); bl[1] = f2t(b1 - __uint_as_float(bh[1]));
                #pragma unroll
                for (int mi = 0; mi < 4; mi++) {
                    mma8(Cacc[mi * 4 + ni], Ah[mi], bh);
                    mma8(Cacc[mi * 4 + ni], Al[mi], bh);
                    mma8(Cacc[mi * 4 + ni], Ah[mi], bl);
                }
            }
        }
        __syncthreads();
    }

    // epilogue: exp + partial sums
    float rs[4][2], cs[4][2];
    #pragma unroll
    for (int i = 0; i < 4; i++) { rs[i][0] = rs[i][1] = 0.f; cs[i][0] = cs[i][1] = 0.f; }
    int mr = lane >> 2, nc = (lane & 3) * 2;
    #pragma unroll
    for (int mi = 0; mi < 4; mi++) {
        int gm0 = bm + wr * 64 + mi * 16 + mr, gm1 = gm0 + 8;
        #pragma unroll
        for (int ni = 0; ni < 4; ni++) {
            int gn0 = bn + wc * 32 + ni * 8 + nc, gn1 = gn0 + 1;
            float* c = Cacc[mi * 4 + ni];
            float e00 = (gm0 < M && gn0 < M) ? __expf(c[0] * 5.f - 5.f) : 0.f;
            float e01 = (gm0 < M && gn1 < M) ? __expf(c[1] * 5.f - 5.f) : 0.f;
            float e10 = (gm1 < M && gn0 < M) ? __expf(c[2] * 5.f - 5.f) : 0.f;
            float e11 = (gm1 < M && gn1 < M) ? __expf(c[3] * 5.f - 5.f) : 0.f;
            rs[mi][0] += e00 + e01; rs[mi][1] += e10 + e11;
            cs[ni][0] += e00 + e10; cs[ni][1] += e01 + e11;
        }
    }
    #pragma unroll
    for (int mi = 0; mi < 4; mi++)
        #pragma unroll
        for (int j = 0; j < 2; j++) {
            rs[mi][j] += __shfl_xor_sync(0xffffffffu, rs[mi][j], 1);
            rs[mi][j] += __shfl_xor_sync(0xffffffffu, rs[mi][j], 2);
        }
    if ((lane & 3) == 0) {
        #pragma unroll
        for (int mi = 0; mi < 4; mi++) {
            redR[wr * 64 + mi * 16 + mr][wc]     = rs[mi][0];
            redR[wr * 64 + mi * 16 + mr + 8][wc] = rs[mi][1];
        }
    }
    #pragma unroll
    for (int ni = 0; ni < 4; ni++)
        #pragma unroll
        for (int j = 0; j < 2; j++) {
            cs[ni][j] += __shfl_xor_sync(0xffffffffu, cs[ni][j], 4);
            cs[ni][j] += __shfl_xor_sync(0xffffffffu, cs[ni][j], 8);
            cs[ni][j] += __shfl_xor_sync(0xffffffffu, cs[ni][j], 16);
        }
    if (mr == 0) {
        #pragma unroll
        for (int ni = 0; ni < 4; ni++) {
            redC[wc * 32 + ni * 8 + nc][wr]     = cs[ni][0];
            redC[wc * 32 + ni * 8 + nc + 1][wr] = cs[ni][1];
        }
    }
    __syncthreads();
    if (t < 128) {
        rowp[(size_t)blockIdx.x * MPAD + bm + t] =
            redR[t][0] + redR[t][1] + redR[t][2] + redR[t][3];
        colp[(size_t)blockIdx.y * MPAD + bn + t] = redC[t][0] + redC[t][1];
    }
}

// =====================================================================
// Compensated-TF32 split-K GEMM, N=128: Cp[s] = A(MxK) @ B(Kx128).
// grid (S, mtiles), 256 threads, block tile 128x128, warp tile 64x32.
// =====================================================================
__global__ __launch_bounds__(256)
void mma_n128_k(const float* __restrict__ A, const float* __restrict__ B,
                float* __restrict__ Cp, int M, int K, int Kc)
{
    __shared__ __align__(16) float As[128][36];
    __shared__ __align__(16) float Bs[32][136];

    int s = blockIdx.x, bm = blockIdx.y * 128;
    int kb = s * Kc;
    int ke = min(K, kb + Kc);
    int t = threadIdx.x, lane = t & 31, w = t >> 5;
    int wr = w >> 2, wc = w & 3;

    float Cacc[16][4];
    #pragma unroll
    for (int f = 0; f < 16; f++)
        #pragma unroll
        for (int q = 0; q < 4; q++) Cacc[f][q] = 0.f;

    for (int kc = kb; kc < ke; kc += 32) {
        int klen = ke - kc;      // may be < 32 at the tail
        #pragma unroll
        for (int i = 0; i < 8; i++) {
            int idx = t + i * 256;
            int row = idx >> 4, c2 = (idx & 15) * 2;
            int gm = bm + row;
            float2 v = make_float2(0.f, 0.f);
            if (gm < M) {
                if (c2 + 1 < klen)      v = *(const float2*)&A[(size_t)gm * K + kc + c2];
                else if (c2 < klen)     v.x = A[(size_t)gm * K + kc + c2];
            }
            As[row][c2] = v.x; As[row][c2 + 1] = v.y;
        }
        #pragma unroll
        for (int i = 0; i < 4; i++) {
            int idx = t + i * 256;
            int kr = idx >> 5, c4 = (idx & 31) * 4;
            float4 v = (kr < klen) ? *(const float4*)&B[(size_t)(kc + kr) * 128 + c4]
                                   : make_float4(0.f, 0.f, 0.f, 0.f);
            *(float4*)&Bs[kr][c4] = v;
        }
        __syncthreads();
        #pragma unroll
        for (int k8 = 0; k8 < 32; k8 += 8) {
            unsigned Ah[4][4], Al[4][4];
            int mrow = lane >> 2, kk = k8 + (lane & 3);
            #pragma unroll
            for (int mi = 0; mi < 4; mi++) {
                int m0 = wr * 64 + mi * 16 + mrow;
                float a0 = As[m0][kk],     a1 = As[m0 + 8][kk];
                float a2 = As[m0][kk + 4], a3 = As[m0 + 8][kk + 4];
                Ah[mi][0] = f2t(a0); Al[mi][0] = f2t(a0 - __uint_as_float(Ah[mi][0]));
                Ah[mi][1] = f2t(a1); Al[mi][1] = f2t(a1 - __uint_as_float(Ah[mi][1]));
                Ah[mi][2] = f2t(a2); Al[mi][2] = f2t(a2 - __uint_as_float(Ah[mi][2]));
                Ah[mi][3] = f2t(a3); Al[mi][3] = f2t(a3 - __uint_as_float(Ah[mi][3]));
            }
            #pragma unroll
            for (int ni = 0; ni < 4; ni++) {
                int n0 = wc * 32 + ni * 8 + mrow;
                float b0 = Bs[kk][n0], b1 = Bs[kk + 4][n0];
                unsigned bh[2], bl[2];
                bh[0] = f2t(b0); bl[0] = f2t(b0 - __uint_as_float(bh[0]));
                bh[1] = f2t(b1); bl[1] = f2t(b1 - __uint_as_float(bh[1]));
                #pragma unroll
                for (int mi = 0; mi < 4; mi++) {
                    mma8(Cacc[mi * 4 + ni], Ah[mi], bh);
                    mma8(Cacc[mi * 4 + ni], Al[mi], bh);
                    mma8(Cacc[mi * 4 + ni], Ah[mi], bl);
                }
            }
        }
        __syncthreads();
    }

    size_t base = (size_t)s * ((size_t)MPAD * 128);
    int mr = lane >> 2, nc = (lane & 3) * 2;
    #pragma unroll
    for (int mi = 0; mi < 4; mi++) {
        int gm0 = bm + wr * 64 + mi * 16 + mr, gm1 = gm0 + 8;
        #pragma unroll
        for (int ni = 0; ni < 4; ni++) {
            int n = wc * 32 + ni * 8 + nc;
            float* c = Cacc[mi * 4 + ni];
            if (gm0 < M) *(float2*)&Cp[base + (size_t)gm0 * 128 + n] = make_float2(c[0], c[1]);
            if (gm1 < M) *(float2*)&Cp[base + (size_t)gm1 * 128 + n] = make_float2(c[2], c[3]);
        }
    }
}

__global__ void comb_n128_k(const float* __restrict__ Cp, int S,
                            float* __restrict__ C, int M, float alpha, int accum)
{
    int i = blockIdx.x * 256 + threadIdx.x;
    if (i >= M * 128) return;
    float s = 0.f;
    for (int q = 0; q < S; q++) s += Cp[(size_t)q * ((size_t)MPAD * 128) + i];
    float v = alpha * s;
    C[i] = accum ? C[i] + v : v;
}

__global__ void lse_comb_k(const float* __restrict__ pp, int ntiles,
                           float* __restrict__ lse, int M)
{
    int r = blockIdx.x * 256 + threadIdx.x;
    if (r >= M) return;
    float s = 0.f;
    for (int q = 0; q < ntiles; q++) s += pp[(size_t)q * MPAD + r];
    lse[r] = 5.f + logf(s);
}

__global__ void diag_k(const float* __restrict__ Z1, const float* __restrict__ Z2,
                       int M, float* __restrict__ dg)
{
    int gt = blockIdx.x * blockDim.x + threadIdx.x;
    int r = gt >> 5, lane = gt & 31;
    if (r >= M) return;
    const float* a = Z1 + (size_t)r * 128;
    const float* b = Z2 + (size_t)r * 128;
    float s = 0.f;
    #pragma unroll
    for (int d = lane; d < 128; d += 32) s += a[d] * b[d];
    #pragma unroll
    for (int off = 16; off; off >>= 1) s += __shfl_down_sync(0xffffffffu, s, off);
    if (lane == 0) dg[r] = 5.f * s;
}

// =====================================================================
// generic FFMA SGEMM (small cases: K=51 hconv, 42x42 NCE)
// =====================================================================
__global__ void sgemm_kernel(const float* __restrict__ A, const float* __restrict__ B,
                             float* __restrict__ C, int M, int N, int K,
                             float alpha, int transB, int accum)
{
    __shared__ __align__(16) float As[16][68];
    __shared__ __align__(16) float Bs[16][68];
    int bm = blockIdx.y * 64, bn = blockIdx.x * 64;
    int t  = threadIdx.x;
    int ty = t >> 4, tx = t & 15;
    float acc[4][4];
    #pragma unroll
    for (int i = 0; i < 4; i++)
        #pragma unroll
        for (int j = 0; j < 4; j++) acc[i][j] = 0.f;

    for (int k0 = 0; k0 < K; k0 += 16) {
        #pragma unroll
        for (int i = 0; i < 4; i++) {
            int e  = t + i * 256;
            int mm = e >> 4, kk = e & 15;
            int gm = bm + mm, gk = k0 + kk;
            As[kk][mm] = (gm < M && gk < K) ? A[(size_t)gm * K + gk] : 0.f;
        }
        if (!transB) {
            #pragma unroll
            for (int i = 0; i < 4; i++) {
                int e  = t + i * 256;
                int kk = e >> 6, nn = e & 63;
                int gk = k0 + kk, gn = bn + nn;
                Bs[kk][nn] = (gk < K && gn < N) ? B[(size_t)gk * N + gn] : 0.f;
            }
        } else {
            #pragma unroll
            for (int i = 0; i < 4; i++) {
                int e  = t + i * 256;
                int nn = e >> 4, kk = e & 15;
                int gn = bn + nn, gk = k0 + kk;
                Bs[kk][nn] = (gn < N && gk < K) ? B[(size_t)gn * K + gk] : 0.f;
            }
        }
        __syncthreads();
        #pragma unroll
        for (int kk = 0; kk < 16; kk++) {
            float4 av = *(const float4*)&As[kk][ty * 4];
            float4 bv = *(const float4*)&Bs[kk][tx * 4];
            float a4[4] = {av.x, av.y, av.z, av.w};
            float b4[4] = {bv.x, bv.y, bv.z, bv.w};
            #pragma unroll
            for (int i = 0; i < 4; i++)
                #pragma unroll
                for (int j = 0; j < 4; j++) acc[i][j] += a4[i] * b4[j];
        }
        __syncthreads();
    }
    #pragma unroll
    for (int i = 0; i < 4; i++) {
        int gm = bm + ty * 4 + i;
        if (gm >= M) continue;
        #pragma unroll
        for (int j = 0; j < 4; j++) {
            int gn = bn + tx * 4 + j;
            if (gn >= N) continue;
            size_t idx = (size_t)gm * N + gn;
            float v = alpha * acc[i][j];
            C[idx] = accum ? (C[idx] + v) : v;
        }
    }
}

// ---- tall-skinny: C(NHE x 128) = A(NHE x K) @ B(K x 128) ----
__global__ void skinny_mm_k(const float* __restrict__ A, const float* __restrict__ B,
                            float* __restrict__ C, int K)
{
    int m = blockIdx.x;
    int t = threadIdx.x;
    int n = t & 127;
    int q = t >> 7;
    const float* a = A + (size_t)m * K;
    float s0 = 0.f, s1 = 0.f;
    for (int k = q; k < K; k += 8) {
        s0 += a[k] * B[(size_t)k * 128 + n];
        int k2 = k + 4;
        if (k2 < K) s1 += a[k2] * B[(size_t)k2 * 128 + n];
    }
    __shared__ float sh[3][128];
    float s = s0 + s1;
    if (q) sh[q - 1][n] = s;
    __syncthreads();
    if (q == 0) C[(size_t)m * 128 + n] = s + sh[0][n] + sh[1][n] + sh[2][n];
}

// ---------------- elementwise ----------------
__global__ void copy_k(float* d, const float* s, int n) {
    int i = blockIdx.x * blockDim.x + threadIdx.x;
    if (i < n) d[i] = s[i];
}
__global__ void add_k(float* d, const float* s, int n) {
    int i = blockIdx.x * blockDim.x + threadIdx.x;
    if (i < n) d[i] += s[i];
}
__global__ void gate_k(const float* __restrict__ w, const float* __restrict__ tm,
                       const float* __restrict__ b, float* __restrict__ out, int n) {
    int i = blockIdx.x * blockDim.x + threadIdx.x;
    if (i >= n) return;
    float z = tm[i] + b[i & 127];
    out[i] = w[i] / (1.f + expf(-z));
}
__global__ void kan_gate_k(const float* __restrict__ G, const float* __restrict__ bias,
                           const float* __restrict__ Xa, const float* __restrict__ Xb,
                           float* __restrict__ f, int n) {
    int i = blockIdx.x * blockDim.x + threadIdx.x;
    if (i >= n) return;
    float g = 1.f / (1.f + expf(-(G[i] + bias[i & 127])));
    f[i] = g * Xa[i] + (1.f - g) * Xb[i];
}
__global__ void buildT_k(const float* __restrict__ Xa, const float* __restrict__ Xb,
                         float* __restrict__ T, int n) {
    int i = blockIdx.x * blockDim.x + threadIdx.x;
    if (i >= n) return;
    int row = i >> 7, c = i & 127;
    float x  = tanhf(Xa[i]);
    float t2 = 2.f * x * x - 1.f;
    float t3 = 2.f * x * t2 - x;
    float* p = T + (size_t)row * CW + c * 3;
    p[0] = x; p[1] = t2; p[2] = t3;
    x  = tanhf(Xb[i]);
    t2 = 2.f * x * x - 1.f;
    t3 = 2.f * x * t2 - x;
    p = T + (size_t)row * CW + 384 + c * 3;
    p[0] = x; p[1] = t2; p[2] = t3;
}

// ---------------- L2 normalize ----------------
__global__ void l2norm_k(const float* __restrict__ x, float* __restrict__ y) {
    int r = blockIdx.x, t = threadIdx.x;
    float v = x[(size_t)r * 128 + t];
    __shared__ float sh[128];
    sh[t] = v * v; __syncthreads();
    for (int st = 64; st; st >>= 1) { if (t < st) sh[t] += sh[t + st]; __syncthreads(); }
    y[(size_t)r * 128 + t] = v / fmaxf(sqrtf(sh[0]), 1e-12f);
}
__global__ void addnorm_k(const float* __restrict__ x, const float* __restrict__ ns,
                          float* __restrict__ y) {
    int r = blockIdx.x, t = threadIdx.x;
    float v = x[(size_t)r * 128 + t] + ns[(size_t)r * 128 + t];
    __shared__ float sh[128];
    sh[t] = v * v; __syncthreads();
    for (int st = 64; st; st >>= 1) { if (t < st) sh[t] += sh[t + st]; __syncthreads(); }
    y[(size_t)r * 128 + t] = v / fmaxf(sqrtf(sh[0]), 1e-12f);
}

// ---------------- small InfoNCE path (NUC only) ----------------
__global__ void row_lse_k(const float* __restrict__ S, float* lse, float* diag, int M) {
    int r = blockIdx.x, t = threadIdx.x;
    const float* row = S + (size_t)r * M;
    float s = 0.f;
    for (int j = t; j < M; j += 128) s += expf(row[j] - 5.0f);
    __shared__ float sh[128];
    sh[t] = s; __syncthreads();
    for (int st = 64; st; st >>= 1) { if (t < st) sh[t] += sh[t + st]; __syncthreads(); }
    if (t == 0) { lse[r] = 5.0f + logf(sh[0]); diag[r] = row[r]; }
}
__global__ void col_part_k(const float* __restrict__ S, int M, int splits) {
    int col = blockIdx.x * 256 + threadIdx.x;
    if (col >= M) return;
    int sp = blockIdx.y;
    long r0 = (long)M * sp / splits, r1 = (long)M * (sp + 1) / splits;
    float s = 0.f;
    for (long r = r0; r < r1; r++) s += expf(S[(size_t)r * M + col] - 5.0f);
    g_psum[sp * NU + col] = s;
}
__global__ void col_comb_k(float* lsec, int M, int splits) {
    int col = blockIdx.x * 256 + threadIdx.x;
    if (col >= M) return;
    float s = 0.f;
    for (int sp = 0; sp < splits; sp++) s += g_psum[sp * NU + col];
    lsec[col] = 5.0f + logf(s);
}
__global__ void nce_accum_k(const float* lr, const float* lc, const float* dg, int M) {
    __shared__ float sh[256];
    int t = threadIdx.x;
    float a = 0.f;
    for (int i = t; i < M; i += 256) a += (lr[i] - dg[i]) + (lc[i] - dg[i]);
    sh[t] = a; __syncthreads();
    for (int st = 128; st; st >>= 1) { if (t < st) sh[t] += sh[t + st]; __syncthreads(); }
    if (t == 0) g_loss += 0.5f * sh[0] / (float)M;
}

// ---------------- setup ----------------
__global__ void setup_tab_k() {
    int i = blockIdx.x * blockDim.x + threadIdx.x;
    if (i >= D * D) return;
    int a = i >> 7, b = i & 127;
    float ang = 6.28318530717958647692f * (float)((a * b) & 127) / 128.f;
    g_tabc[i] = cosf(ang);
    g_tabs[i] = sinf(ang);
}
__global__ void pack_cheb_k(const float* __restrict__ cr, const float* __restrict__ ci) {
    int i = blockIdx.x * blockDim.x + threadIdx.x;
    if (i >= CW * D) return;
    int r = i >> 7, o = i & 127;
    int rr = r % 384;
    int ii = rr / 3, k = rr % 3 + 1;
    g_CrP[i] = cr[((size_t)ii * 128 + o) * 4 + k];
    g_CiP[i] = ci[((size_t)ii * 128 + o) * 4 + k];
}
__global__ void bias_k(const float* __restrict__ cr, const float* __restrict__ ci) {
    int o = threadIdx.x;
    float s1 = 0.f, s2 = 0.f;
    for (int ii = 0; ii < 128; ii++) {
        s1 += cr[((size_t)ii * 128 + o) * 4];
        s2 += ci[((size_t)ii * 128 + o) * 4];
    }
    g_br[o] = 2.f * s1;
    g_bi[o] = 2.f * s2;
    if (o == 0) g_loss = 0.f;
}

// ---------------- finals ----------------
__global__ void finalu_k(const int* __restrict__ uui, const int* __restrict__ ucol) {
    int d = threadIdx.x;
    g_fu[d] = g_ue[(size_t)(*uui) * 128 + d] + g_hus[(size_t)(*ucol) * 128 + d];
}
__global__ void outvec_k(const float* __restrict__ fp, float* __restrict__ out) {
    int gt = blockIdx.x * blockDim.x + threadIdx.x;
    int w = gt >> 5, lane = gt & 31;
    if (w >= P) return;
    const float* row = fp + (size_t)w * 128;
    float s = 0.f;
    #pragma unroll
    for (int d = lane; d < 128; d += 32) s += row[d] * g_fu[d];
    #pragma unroll
    for (int off = 16; off; off >>= 1) s += __shfl_down_sync(0xffffffffu, s, off);
    if (lane == 0) out[w] = s;
}
__global__ void final_k(float* __restrict__ dout, const int* __restrict__ target) {
    __shared__ float sm[1024], ss[1024];
    int t = threadIdx.x;
    float m = -1e30f, s = 0.f;
    for (int j = t; j < P; j += 1024) {
        float x = dout[1 + j];
        float nm = fmaxf(m, x);
        s = s * expf(m - nm) + expf(x - nm);
        m = nm;
    }
    sm[t] = m; ss[t] = s; __syncthreads();
    for (int st = 512; st; st >>= 1) {
        if (t < st) {
            float m2 = sm[t + st], s2 = ss[t + st];
            float nm = fmaxf(sm[t], m2);
            ss[t] = ss[t] * expf(sm[t] - nm) + s2 * expf(m2 - nm);
            sm[t] = nm;
        }
        __syncthreads();
    }
    if (t == 0) {
        float lse = sm[0] + logf(ss[0]);
        dout[0] = (lse - dout[1 + (*target)]) + g_loss;
    }
}

// ---------------- host orchestration ----------------
static inline dim3 ew(int n) { return dim3((n + 255) / 256); }

#define GSYM(p, s) do { void* _q = nullptr; cudaGetSymbolAddress(&_q, s); p = (float*)_q; } while (0)

static float *s_part;

static void gemm128(const float* A, const float* B, float* C, int M, int K, int S,
                    float alpha, bool accum)
{
    int Kc = (((K + S - 1) / S) + 31) & ~31;
    dim3 g(S, (M + 127) / 128);
    mma_n128_k<<<g, 256>>>(A, B, s_part, M, K, Kc);
    comb_n128_k<<<ew(M * 128), 256>>>(s_part, S, C, M, alpha, accum ? 1 : 0);
}

static void run_nce(const float* Z1, const float* Z2, int M,
                    float* rp, float* cp, float* lr, float* lc, float* dg)
{
    int nt = (M + 127) / 128;
    dim3 g(nt, nt);
    nce_mma_k<<<g, 256>>>(Z1, Z2, M, rp, cp);
    lse_comb_k<<<ew(M), 256>>>(rp, nt, lr, M);
    lse_comb_k<<<ew(M), 256>>>(cp, nt, lc, M);
    diag_k<<<(M * 32 + 255) / 256, 256>>>(Z1, Z2, M, dg);
    nce_accum_k<<<1, 256>>>(lr, lc, dg, M);
}

extern "C" void kernel_launch(void* const* d_in, const int* in_sizes, int n_in,
                              void* d_out, int out_size)
{
    const float* poi_w    = (const float*)d_in[0];
    const float* ui_w     = (const float*)d_in[1];
    const float* w_gc     = (const float*)d_in[2];
    const float* b_gc     = (const float*)d_in[3];
    const float* w_gU     = (const float*)d_in[4];
    const float* b_gU     = (const float*)d_in[5];
    const float* cheb_r   = (const float*)d_in[6];
    const float* cheb_i   = (const float*)d_in[7];
    const float* HG_pu    = (const float*)d_in[8];
    const float* HG_up    = (const float*)d_in[9];
    const float* U_I      = (const float*)d_in[10];
    const float* noise1   = (const float*)d_in[11];
    const float* noise2   = (const float*)d_in[12];
    const int*   target   = (const int*)d_in[13];
    const int*   user_col = (const int*)d_in[14];
    const int*   user_ui  = (const int*)d_in[15];
    float* out = (float*)d_out;

    float *A, *B, *C2, *acc, *hg, *z2a, *uA, *uB, *uC, *uacc, *ue, *z2b;
    float *hus, *ucl, *X1r, *X1i, *X2r, *X2i, *Tr, *Ti, *Gr, *Gi, *fr, *fi, *fp;
    float *lr, *lc, *dg, *tabc, *tabs, *CrP, *CiP, *br, *bi, *rp, *cp;
    GSYM(A, g_A); GSYM(B, g_B); GSYM(C2, g_C2); GSYM(acc, g_acc);
    GSYM(hg, g_hg); GSYM(z2a, g_z2a);
    GSYM(uA, g_uA); GSYM(uB, g_uB); GSYM(uC, g_uC); GSYM(uacc, g_uacc);
    GSYM(ue, g_ue); GSYM(z2b, g_z2b);
    GSYM(hus, g_hus); GSYM(ucl, g_ucl);
    GSYM(X1r, g_X1r); GSYM(X1i, g_X1i); GSYM(X2r, g_X2r); GSYM(X2i, g_X2i);
    GSYM(Tr, g_Tr); GSYM(Ti, g_Ti); GSYM(Gr, g_Gr); GSYM(Gi, g_Gi);
    GSYM(fr, g_fr); GSYM(fi, g_fi); GSYM(fp, g_fp);
    GSYM(lr, g_lr); GSYM(lc, g_lc); GSYM(dg, g_dg);
    GSYM(tabc, g_tabc); GSYM(tabs, g_tabs); GSYM(CrP, g_CrP); GSYM(CiP, g_CiP);
    GSYM(br, g_br); GSYM(bi, g_bi); GSYM(rp, g_rp); GSYM(cp, g_cp);
    GSYM(s_part, g_part);

    // setup (also zeroes loss accumulator)
    setup_tab_k<<<ew(D * D), 256>>>();
    pack_cheb_k<<<ew(CW * D), 256>>>(cheb_r, cheb_i);
    bias_k<<<1, 128>>>(cheb_r, cheb_i);

    // gated embeddings
    gemm128(poi_w, w_gc, B, P, 128, 4, 1.f, false);
    gate_k<<<ew(P * D), 256>>>(poi_w, B, b_gc, A, P * D);
    gemm128(ui_w, w_gU, uB, NU, 128, 4, 1.f, false);
    gate_k<<<ew(NU * D), 256>>>(ui_w, uB, b_gU, uA, NU * D);

    // hconv (2 layers) -> hg
    copy_k<<<ew(P * D), 256>>>(acc, A, P * D);
    skinny_mm_k<<<NHE, 512>>>(HG_pu, A, hus, P);
    { dim3 g(2, 128); sgemm_kernel<<<g, 256>>>(HG_up, hus, B, P, 128, NHE, 1.f, 0, 0); }
    add_k<<<ew(P * D), 256>>>(acc, B, P * D);
    skinny_mm_k<<<NHE, 512>>>(HG_pu, B, hus, P);
    { dim3 g(2, 128); sgemm_kernel<<<g, 256>>>(HG_up, hus, C2, P, 128, NHE, 1.f, 0, 0); }
    add_k<<<ew(P * D), 256>>>(acc, C2, P * D);
    l2norm_k<<<P, 128>>>(acc, hg);
    addnorm_k<<<P, 128>>>(hg, noise1, z2a);

    // level_loss = info_nce(hg, hg+noise1)
    run_nce(hg, z2a, P, rp, cp, lr, lc, dg);

    // hg_users
    skinny_mm_k<<<NHE, 512>>>(HG_pu, hg, hus, P);

    // gconv (2 layers) -> ue
    copy_k<<<ew(NU * D), 256>>>(uacc, uA, NU * D);
    gemm128(U_I, uA, uB, NU, NU, 8, 1.f, false);
    add_k<<<ew(NU * D), 256>>>(uacc, uB, NU * D);
    gemm128(U_I, uB, uC, NU, NU, 8, 1.f, false);
    add_k<<<ew(NU * D), 256>>>(uacc, uC, NU * D);
    l2norm_k<<<NU, 128>>>(uacc, ue);
    addnorm_k<<<NU, 128>>>(ue, noise2, z2b);

    // level_loss1 = info_nce(ue, ue+noise2)
    run_nce(ue, z2b, NU, rp, cp, lr, lc, dg);

    const float* poi_e = ue + (size_t)NUC * D;

    // ssl_p = info_nce(hg, poi_e)
    run_nce(hg, poi_e, P, rp, cp, lr, lc, dg);

    // ssl = info_nce(ue[0:42], l2norm(hg_users[9:]))  (small path)
    l2norm_k<<<NUC, 128>>>(hus + 9 * D, ucl);
    { dim3 g(1, 1); sgemm_kernel<<<g, 256>>>(ue, ucl, s_part, NUC, NUC, 128, 5.f, 1, 0); }
    row_lse_k<<<NUC, 128>>>(s_part, lr, dg, NUC);
    { dim3 g(1, 1); col_part_k<<<g, 256>>>(s_part, NUC, 1); }
    col_comb_k<<<1, 256>>>(lc, NUC, 1);
    nce_accum_k<<<1, 256>>>(lr, lc, dg, NUC);

    // gated KAN: DFT -> cheby gate -> IDFT
    gemm128(hg, tabc, X1r, P, 128, 4,  1.f, false);
    gemm128(hg, tabs, X1i, P, 128, 4, -1.f, false);
    gemm128(poi_e, tabc, X2r, P, 128, 4,  1.f, false);
    gemm128(poi_e, tabs, X2i, P, 128, 4, -1.f, false);
    buildT_k<<<ew(P * D), 256>>>(X1r, X2r, Tr, P * D);
    buildT_k<<<ew(P * D), 256>>>(X1i, X2i, Ti, P * D);
    gemm128(Tr, CrP, Gr, P, CW, 4, 1.f, false);
    gemm128(Ti, CiP, Gi, P, CW, 4, 1.f, false);
    kan_gate_k<<<ew(P * D), 256>>>(Gr, br, X1r, X2r, fr, P * D);
    kan_gate_k<<<ew(P * D), 256>>>(Gi, bi, X1i, X2i, fi, P * D);
    gemm128(fr, tabc, fp, P, 128, 4,  1.f / 128.f, false);
    gemm128(fi, tabs, fp, P, 128, 4, -1.f / 128.f, true);

    // final user vector, logits, loss
    finalu_k<<<1, 128>>>(user_ui, user_col);
    outvec_k<<<(P * 32 + 255) / 256, 256>>>(fp, out + 1);
    final_k<<<1, 1024>>>(out, target);
}

// round 4
// speedup vs baseline: 1.2684x; 1.2684x over previous
#include <cuda_runtime.h>
#include <math.h>

#define P    8192
#define D    128
#define NU   8234
#define NHE  51
#define NUC  42
#define CW   768
#define MPAD 8320
#define NT   65

// ---------------- device scratch ----------------
__device__ float g_A[P*D];
__device__ float g_B[P*D];
__device__ float g_C2[P*D];
__device__ float g_acc[P*D];
__device__ float g_hg[P*D];
__device__ float g_z2a[P*D];
__device__ float g_uA[NU*D];
__device__ float g_uB[NU*D];
__device__ float g_uC[NU*D];
__device__ float g_uacc[NU*D];
__device__ float g_ue[NU*D];
__device__ float g_z2b[NU*D];
__device__ float g_hus[NHE*D];
__device__ float g_ucl[NUC*D];
__device__ float g_X1r[P*D], g_X1i[P*D], g_X2r[P*D], g_X2i[P*D];
__device__ float g_Tr[(size_t)P*CW], g_Ti[(size_t)P*CW];
__device__ float g_Gr[P*D], g_Gi[P*D];
__device__ float g_fr[P*D], g_fi[P*D];
__device__ float g_fp[P*D];
__device__ float g_part[(size_t)8*MPAD*128];
__device__ float g_rp[(size_t)NT*MPAD];
__device__ float g_cp[(size_t)NT*MPAD];
__device__ float g_lr[NU], g_lc[NU], g_dg[NU];
__device__ float g_psum[8*NU];
__device__ float g_tabc[D*D], g_tabs[D*D];
__device__ float g_CrP[CW*D], g_CiP[CW*D];
__device__ float g_br[D], g_bi[D];
__device__ float g_fu[D];
__device__ float g_loss;

// =====================================================================
// Fused InfoNCE, double-buffered: sim = 5*Z1@Z2^T (K=128), exp(sim-5),
// per-tile row/col partial sums only. grid (nt,nt), 256 thr, 128x128.
// =====================================================================
__global__ __launch_bounds__(256, 2)
void nce_fused_k(const float* __restrict__ Z1, const float* __restrict__ Z2,
                 int M, float* __restrict__ rowp, float* __restrict__ colp)
{
    __shared__ __align__(16) float As[2][16][132];
    __shared__ __align__(16) float Bs[2][16][132];
    __shared__ __align__(16) float red[128][17];

    int bm = blockIdx.y * 128, bn = blockIdx.x * 128;
    int t = threadIdx.x, tx = t & 15, ty = t >> 4;
    float acc[8][8];
    #pragma unroll
    for (int i = 0; i < 8; i++)
        #pragma unroll
        for (int j = 0; j < 8; j++) acc[i][j] = 0.f;

    float4 ra[2], rb[2];

    // prologue: load tile 0 into buffer 0
    #pragma unroll
    for (int i = 0; i < 2; i++) {
        int f = t + i * 256, row = f >> 2, c4 = (f & 3) * 4;
        int gm = bm + row;
        ra[i] = (gm < M) ? *(const float4*)&Z1[(size_t)gm * 128 + c4]
                         : make_float4(0.f, 0.f, 0.f, 0.f);
        int gn = bn + row;
        rb[i] = (gn < M) ? *(const float4*)&Z2[(size_t)gn * 128 + c4]
                         : make_float4(0.f, 0.f, 0.f, 0.f);
    }
    #pragma unroll
    for (int i = 0; i < 2; i++) {
        int f = t + i * 256, row = f >> 2, c4 = (f & 3) * 4;
        As[0][c4 + 0][row] = ra[i].x; As[0][c4 + 1][row] = ra[i].y;
        As[0][c4 + 2][row] = ra[i].z; As[0][c4 + 3][row] = ra[i].w;
        Bs[0][c4 + 0][row] = rb[i].x; Bs[0][c4 + 1][row] = rb[i].y;
        Bs[0][c4 + 2][row] = rb[i].z; Bs[0][c4 + 3][row] = rb[i].w;
    }
    __syncthreads();

    #pragma unroll 1
    for (int kt = 0; kt < 8; kt++) {
        int cur = kt & 1;
        if (kt < 7) {
            int k0 = (kt + 1) * 16;
            #pragma unroll
            for (int i = 0; i < 2; i++) {
                int f = t + i * 256, row = f >> 2, c4 = (f & 3) * 4;
                int gm = bm + row;
                ra[i] = (gm < M) ? *(const float4*)&Z1[(size_t)gm * 128 + k0 + c4]
                                 : make_float4(0.f, 0.f, 0.f, 0.f);
                int gn = bn + row;
                rb[i] = (gn < M) ? *(const float4*)&Z2[(size_t)gn * 128 + k0 + c4]
                                 : make_float4(0.f, 0.f, 0.f, 0.f);
            }
        }
        #pragma unroll
        for (int kk = 0; kk < 16; kk++) {
            float a[8], b[8];
            *(float4*)&a[0] = *(const float4*)&As[cur][kk][ty * 8];
            *(float4*)&a[4] = *(const float4*)&As[cur][kk][ty * 8 + 4];
            *(float4*)&b[0] = *(const float4*)&Bs[cur][kk][tx * 8];
            *(float4*)&b[4] = *(const float4*)&Bs[cur][kk][tx * 8 + 4];
            #pragma unroll
            for (int i = 0; i < 8; i++)
                #pragma unroll
                for (int j = 0; j < 8; j++) acc[i][j] += a[i] * b[j];
        }
        if (kt < 7) {
            int nb = 1 - cur;
            #pragma unroll
            for (int i = 0; i < 2; i++) {
                int f = t + i * 256, row = f >> 2, c4 = (f & 3) * 4;
                As[nb][c4 + 0][row] = ra[i].x; As[nb][c4 + 1][row] = ra[i].y;
                As[nb][c4 + 2][row] = ra[i].z; As[nb][c4 + 3][row] = ra[i].w;
                Bs[nb][c4 + 0][row] = rb[i].x; Bs[nb][c4 + 1][row] = rb[i].y;
                Bs[nb][c4 + 2][row] = rb[i].z; Bs[nb][c4 + 3][row] = rb[i].w;
            }
            __syncthreads();
        }
    }

    // epilogue: exp + row/col partial sums
    float rs[8], cs[8];
    #pragma unroll
    for (int i = 0; i < 8; i++) { rs[i] = 0.f; cs[i] = 0.f; }
    #pragma unroll
    for (int i = 0; i < 8; i++) {
        int gm = bm + ty * 8 + i;
        #pragma unroll
        for (int j = 0; j < 8; j++) {
            int gn = bn + tx * 8 + j;
            float e = 0.f;
            if (gm < M && gn < M) e = __expf(acc[i][j] * 5.f - 5.f);
            rs[i] += e; cs[j] += e;
        }
    }
    __syncthreads();
    #pragma unroll
    for (int i = 0; i < 8; i++) red[ty * 8 + i][tx] = rs[i];
    __syncthreads();
    if (t < 128) {
        float s = 0.f;
        #pragma unroll
        for (int q = 0; q < 16; q++) s += red[t][q];
        rowp[(size_t)blockIdx.x * MPAD + bm + t] = s;
    }
    __syncthreads();
    #pragma unroll
    for (int j = 0; j < 8; j++) red[tx * 8 + j][ty] = cs[j];
    __syncthreads();
    if (t < 128) {
        float s = 0.f;
        #pragma unroll
        for (int q = 0; q < 16; q++) s += red[t][q];
        colp[(size_t)blockIdx.y * MPAD + bn + t] = s;
    }
}

__global__ void lse_comb_k(const float* __restrict__ pp, int ntiles,
                           float* __restrict__ lse, int M)
{
    int r = blockIdx.x * 256 + threadIdx.x;
    if (r >= M) return;
    float s = 0.f;
    for (int q = 0; q < ntiles; q++) s += pp[(size_t)q * MPAD + r];
    lse[r] = 5.f + logf(s);
}

__global__ void diag_k(const float* __restrict__ Z1, const float* __restrict__ Z2,
                       int M, float* __restrict__ dg)
{
    int gt = blockIdx.x * blockDim.x + threadIdx.x;
    int r = gt >> 5, lane = gt & 31;
    if (r >= M) return;
    const float* a = Z1 + (size_t)r * 128;
    const float* b = Z2 + (size_t)r * 128;
    float s = 0.f;
    #pragma unroll
    for (int d = lane; d < 128; d += 32) s += a[d] * b[d];
    #pragma unroll
    for (int off = 16; off; off >>= 1) s += __shfl_down_sync(0xffffffffu, s, off);
    if (lane == 0) dg[r] = 5.f * s;
}

// =====================================================================
// Double-buffered split-K GEMM, N=128: Cp[s] = A(MxK) @ B(Kx128).
// grid (S, mtiles), 256 threads, 128x128 tile, 8x8 microtile, BK=16.
// =====================================================================
__global__ __launch_bounds__(256, 2)
void gemm_n128_k(const float* __restrict__ A, const float* __restrict__ B,
                 float* __restrict__ Cp, int M, int K, int Kc)
{
    __shared__ __align__(16) float As[2][16][132];
    __shared__ __align__(16) float Bs[2][16][132];
    int s = blockIdx.x, bm = blockIdx.y * 128;
    int kb = s * Kc;
    int ke = min(K, kb + Kc);
    int nt = (ke > kb) ? (ke - kb + 15) / 16 : 0;
    int t = threadIdx.x, tx = t & 15, ty = t >> 4;
    float acc[8][8];
    #pragma unroll
    for (int i = 0; i < 8; i++)
        #pragma unroll
        for (int j = 0; j < 8; j++) acc[i][j] = 0.f;

    float2 ra[4];
    float4 rb[2];

    if (nt > 0) {
        int k0 = kb, klen = min(16, ke - k0);
        #pragma unroll
        for (int i = 0; i < 4; i++) {
            int f = t + i * 256, row = f >> 3, c2 = (f & 7) * 2;
            int gm = bm + row;
            float2 v = make_float2(0.f, 0.f);
            if (gm < M) {
                if (c2 + 1 < klen)  v = *(const float2*)&A[(size_t)gm * K + k0 + c2];
                else if (c2 < klen) v.x = A[(size_t)gm * K + k0 + c2];
            }
            As[0][c2][row] = v.x; As[0][c2 + 1][row] = v.y;
        }
        #pragma unroll
        for (int i = 0; i < 2; i++) {
            int f = t + i * 256, kk = f >> 5, c4 = (f & 31) * 4;
            float4 v = (kk < klen) ? *(const float4*)&B[(size_t)(k0 + kk) * 128 + c4]
                                   : make_float4(0.f, 0.f, 0.f, 0.f);
            *(float4*)&Bs[0][kk][c4] = v;
        }
        __syncthreads();
    }

    for (int kt = 0; kt < nt; kt++) {
        int cur = kt & 1;
        if (kt + 1 < nt) {
            int k0 = kb + (kt + 1) * 16, klen = min(16, ke - k0);
            #pragma unroll
            for (int i = 0; i < 4; i++) {
                int f = t + i * 256, row = f >> 3, c2 = (f & 7) * 2;
                int gm = bm + row;
                float2 v = make_float2(0.f, 0.f);
                if (gm < M) {
                    if (c2 + 1 < klen)  v = *(const float2*)&A[(size_t)gm * K + k0 + c2];
                    else if (c2 < klen) v.x = A[(size_t)gm * K + k0 + c2];
                }
                ra[i] = v;
            }
            #pragma unroll
            for (int i = 0; i < 2; i++) {
                int f = t + i * 256, kk = f >> 5, c4 = (f & 31) * 4;
                rb[i] = (kk < klen) ? *(const float4*)&B[(size_t)(k0 + kk) * 128 + c4]
                                    : make_float4(0.f, 0.f, 0.f, 0.f);
            }
        }
        #pragma unroll
        for (int kk = 0; kk < 16; kk++) {
            float a[8], b[8];
            *(float4*)&a[0] = *(const float4*)&As[cur][kk][ty * 8];
            *(float4*)&a[4] = *(const float4*)&As[cur][kk][ty * 8 + 4];
            *(float4*)&b[0] = *(const float4*)&Bs[cur][kk][tx * 8];
            *(float4*)&b[4] = *(const float4*)&Bs[cur][kk][tx * 8 + 4];
            #pragma unroll
            for (int i = 0; i < 8; i++)
                #pragma unroll
                for (int j = 0; j < 8; j++) acc[i][j] += a[i] * b[j];
        }
        if (kt + 1 < nt) {
            int nb = 1 - cur;
            #pragma unroll
            for (int i = 0; i < 4; i++) {
                int f = t + i * 256, row = f >> 3, c2 = (f & 7) * 2;
                As[nb][c2][row] = ra[i].x; As[nb][c2 + 1][row] = ra[i].y;
            }
            #pragma unroll
            for (int i = 0; i < 2; i++) {
                int f = t + i * 256, kk = f >> 5, c4 = (f & 31) * 4;
                *(float4*)&Bs[nb][kk][c4] = rb[i];
            }
            __syncthreads();
        }
    }

    size_t base = (size_t)s * ((size_t)MPAD * 128);
    #pragma unroll
    for (int i = 0; i < 8; i++) {
        int gm = bm + ty * 8 + i;
        if (gm >= M) continue;
        *(float4*)&Cp[base + (size_t)gm * 128 + tx * 8]     = *(float4*)&acc[i][0];
        *(float4*)&Cp[base + (size_t)gm * 128 + tx * 8 + 4] = *(float4*)&acc[i][4];
    }
}

__global__ void comb_n128_k(const float* __restrict__ Cp, int S,
                            float* __restrict__ C, int M, float alpha, int accum)
{
    int i = blockIdx.x * 256 + threadIdx.x;
    if (i >= M * 128) return;
    float s = 0.f;
    for (int q = 0; q < S; q++) s += Cp[(size_t)q * ((size_t)MPAD * 128) + i];
    float v = alpha * s;
    C[i] = accum ? C[i] + v : v;
}

// =====================================================================
// generic FFMA SGEMM (small cases: K=51 hconv, 42x42 NCE)
// =====================================================================
__global__ void sgemm_kernel(const float* __restrict__ A, const float* __restrict__ B,
                             float* __restrict__ C, int M, int N, int K,
                             float alpha, int transB, int accum)
{
    __shared__ __align__(16) float As[16][68];
    __shared__ __align__(16) float Bs[16][68];
    int bm = blockIdx.y * 64, bn = blockIdx.x * 64;
    int t  = threadIdx.x;
    int ty = t >> 4, tx = t & 15;
    float acc[4][4];
    #pragma unroll
    for (int i = 0; i < 4; i++)
        #pragma unroll
        for (int j = 0; j < 4; j++) acc[i][j] = 0.f;

    for (int k0 = 0; k0 < K; k0 += 16) {
        #pragma unroll
        for (int i = 0; i < 4; i++) {
            int e  = t + i * 256;
            int mm = e >> 4, kk = e & 15;
            int gm = bm + mm, gk = k0 + kk;
            As[kk][mm] = (gm < M && gk < K) ? A[(size_t)gm * K + gk] : 0.f;
        }
        if (!transB) {
            #pragma unroll
            for (int i = 0; i < 4; i++) {
                int e  = t + i * 256;
                int kk = e >> 6, nn = e & 63;
                int gk = k0 + kk, gn = bn + nn;
                Bs[kk][nn] = (gk < K && gn < N) ? B[(size_t)gk * N + gn] : 0.f;
            }
        } else {
            #pragma unroll
            for (int i = 0; i < 4; i++) {
                int e  = t + i * 256;
                int nn = e >> 4, kk = e & 15;
                int gn = bn + nn, gk = k0 + kk;
                Bs[kk][nn] = (gn < N && gk < K) ? B[(size_t)gn * K + gk] : 0.f;
            }
        }
        __syncthreads();
        #pragma unroll
        for (int kk = 0; kk < 16; kk++) {
            float4 av = *(const float4*)&As[kk][ty * 4];
            float4 bv = *(const float4*)&Bs[kk][tx * 4];
            float a4[4] = {av.x, av.y, av.z, av.w};
            float b4[4] = {bv.x, bv.y, bv.z, bv.w};
            #pragma unroll
            for (int i = 0; i < 4; i++)
                #pragma unroll
                for (int j = 0; j < 4; j++) acc[i][j] += a4[i] * b4[j];
        }
        __syncthreads();
    }
    #pragma unroll
    for (int i = 0; i < 4; i++) {
        int gm = bm + ty * 4 + i;
        if (gm >= M) continue;
        #pragma unroll
        for (int j = 0; j < 4; j++) {
            int gn = bn + tx * 4 + j;
            if (gn >= N) continue;
            size_t idx = (size_t)gm * N + gn;
            float v = alpha * acc[i][j];
            C[idx] = accum ? (C[idx] + v) : v;
        }
    }
}

// ---- tall-skinny: C(NHE x 128) = A(NHE x K) @ B(K x 128) ----
__global__ void skinny_mm_k(const float* __restrict__ A, const float* __restrict__ B,
                            float* __restrict__ C, int K)
{
    int m = blockIdx.x;
    int t = threadIdx.x;
    int n = t & 127;
    int q = t >> 7;
    const float* a = A + (size_t)m * K;
    float s0 = 0.f, s1 = 0.f;
    for (int k = q; k < K; k += 8) {
        s0 += a[k] * B[(size_t)k * 128 + n];
        int k2 = k + 4;
        if (k2 < K) s1 += a[k2] * B[(size_t)k2 * 128 + n];
    }
    __shared__ float sh[3][128];
    float s = s0 + s1;
    if (q) sh[q - 1][n] = s;
    __syncthreads();
    if (q == 0) C[(size_t)m * 128 + n] = s + sh[0][n] + sh[1][n] + sh[2][n];
}

// ---------------- elementwise ----------------
__global__ void copy_k(float* d, const float* s, int n) {
    int i = blockIdx.x * blockDim.x + threadIdx.x;
    if (i < n) d[i] = s[i];
}
__global__ void add_k(float* d, const float* s, int n) {
    int i = blockIdx.x * blockDim.x + threadIdx.x;
    if (i < n) d[i] += s[i];
}
__global__ void gate_k(const float* __restrict__ w, const float* __restrict__ tm,
                       const float* __restrict__ b, float* __restrict__ out, int n) {
    int i = blockIdx.x * blockDim.x + threadIdx.x;
    if (i >= n) return;
    float z = tm[i] + b[i & 127];
    out[i] = w[i] / (1.f + expf(-z));
}
__global__ void kan_gate_k(const float* __restrict__ G, const float* __restrict__ bias,
                           const float* __restrict__ Xa, const float* __restrict__ Xb,
                           float* __restrict__ f, int n) {
    int i = blockIdx.x * blockDim.x + threadIdx.x;
    if (i >= n) return;
    float g = 1.f / (1.f + expf(-(G[i] + bias[i & 127])));
    f[i] = g * Xa[i] + (1.f - g) * Xb[i];
}
__global__ void buildT_k(const float* __restrict__ Xa, const float* __restrict__ Xb,
                         float* __restrict__ T, int n) {
    int i = blockIdx.x * blockDim.x + threadIdx.x;
    if (i >= n) return;
    int row = i >> 7, c = i & 127;
    float x  = tanhf(Xa[i]);
    float t2 = 2.f * x * x - 1.f;
    float t3 = 2.f * x * t2 - x;
    float* p = T + (size_t)row * CW + c * 3;
    p[0] = x; p[1] = t2; p[2] = t3;
    x  = tanhf(Xb[i]);
    t2 = 2.f * x * x - 1.f;
    t3 = 2.f * x * t2 - x;
    p = T + (size_t)row * CW + 384 + c * 3;
    p[0] = x; p[1] = t2; p[2] = t3;
}

// ---------------- L2 normalize ----------------
__global__ void l2norm_k(const float* __restrict__ x, float* __restrict__ y) {
    int r = blockIdx.x, t = threadIdx.x;
    float v = x[(size_t)r * 128 + t];
    __shared__ float sh[128];
    sh[t] = v * v; __syncthreads();
    for (int st = 64; st; st >>= 1) { if (t < st) sh[t] += sh[t + st]; __syncthreads(); }
    y[(size_t)r * 128 + t] = v / fmaxf(sqrtf(sh[0]), 1e-12f);
}
__global__ void addnorm_k(const float* __restrict__ x, const float* __restrict__ ns,
                          float* __restrict__ y) {
    int r = blockIdx.x, t = threadIdx.x;
    float v = x[(size_t)r * 128 + t] + ns[(size_t)r * 128 + t];
    __shared__ float sh[128];
    sh[t] = v * v; __syncthreads();
    for (int st = 64; st; st >>= 1) { if (t < st) sh[t] += sh[t + st]; __syncthreads(); }
    y[(size_t)r * 128 + t] = v / fmaxf(sqrtf(sh[0]), 1e-12f);
}

// ---------------- small InfoNCE path (NUC only) ----------------
__global__ void row_lse_k(const float* __restrict__ S, float* lse, float* diag, int M) {
    int r = blockIdx.x, t = threadIdx.x;
    const float* row = S + (size_t)r * M;
    float s = 0.f;
    for (int j = t; j < M; j += 128) s += expf(row[j] - 5.0f);
    __shared__ float sh[128];
    sh[t] = s; __syncthreads();
    for (int st = 64; st; st >>= 1) { if (t < st) sh[t] += sh[t + st]; __syncthreads(); }
    if (t == 0) { lse[r] = 5.0f + logf(sh[0]); diag[r] = row[r]; }
}
__global__ void col_part_k(const float* __restrict__ S, int M, int splits) {
    int col = blockIdx.x * 256 + threadIdx.x;
    if (col >= M) return;
    int sp = blockIdx.y;
    long r0 = (long)M * sp / splits, r1 = (long)M * (sp + 1) / splits;
    float s = 0.f;
    for (long r = r0; r < r1; r++) s += expf(S[(size_t)r * M + col] - 5.0f);
    g_psum[sp * NU + col] = s;
}
__global__ void col_comb_k(float* lsec, int M, int splits) {
    int col = blockIdx.x * 256 + threadIdx.x;
    if (col >= M) return;
    float s = 0.f;
    for (int sp = 0; sp < splits; sp++) s += g_psum[sp * NU + col];
    lsec[col] = 5.0f + logf(s);
}
__global__ void nce_accum_k(const float* lr, const float* lc, const float* dg, int M) {
    __shared__ float sh[256];
    int t = threadIdx.x;
    float a = 0.f;
    for (int i = t; i < M; i += 256) a += (lr[i] - dg[i]) + (lc[i] - dg[i]);
    sh[t] = a; __syncthreads();
    for (int st = 128; st; st >>= 1) { if (t < st) sh[t] += sh[t + st]; __syncthreads(); }
    if (t == 0) g_loss += 0.5f * sh[0] / (float)M;
}

// ---------------- setup ----------------
__global__ void setup_tab_k() {
    int i = blockIdx.x * blockDim.x + threadIdx.x;
    if (i >= D * D) return;
    int a = i >> 7, b = i & 127;
    float ang = 6.28318530717958647692f * (float)((a * b) & 127) / 128.f;
    g_tabc[i] = cosf(ang);
    g_tabs[i] = sinf(ang);
}
__global__ void pack_cheb_k(const float* __restrict__ cr, const float* __restrict__ ci) {
    int i = blockIdx.x * blockDim.x + threadIdx.x;
    if (i >= CW * D) return;
    int r = i >> 7, o = i & 127;
    int rr = r % 384;
    int ii = rr / 3, k = rr % 3 + 1;
    g_CrP[i] = cr[((size_t)ii * 128 + o) * 4 + k];
    g_CiP[i] = ci[((size_t)ii * 128 + o) * 4 + k];
}
__global__ void bias_k(const float* __restrict__ cr, const float* __restrict__ ci) {
    int o = threadIdx.x;
    float s1 = 0.f, s2 = 0.f;
    for (int ii = 0; ii < 128; ii++) {
        s1 += cr[((size_t)ii * 128 + o) * 4];
        s2 += ci[((size_t)ii * 128 + o) * 4];
    }
    g_br[o] = 2.f * s1;
    g_bi[o] = 2.f * s2;
    if (o == 0) g_loss = 0.f;
}

// ---------------- finals ----------------
__global__ void finalu_k(const int* __restrict__ uui, const int* __restrict__ ucol) {
    int d = threadIdx.x;
    g_fu[d] = g_ue[(size_t)(*uui) * 128 + d] + g_hus[(size_t)(*ucol) * 128 + d];
}
__global__ void outvec_k(const float* __restrict__ fp, float* __restrict__ out) {
    int gt = blockIdx.x * blockDim.x + threadIdx.x;
    int w = gt >> 5, lane = gt & 31;
    if (w >= P) return;
    const float* row = fp + (size_t)w * 128;
    float s = 0.f;
    #pragma unroll
    for (int d = lane; d < 128; d += 32) s += row[d] * g_fu[d];
    #pragma unroll
    for (int off = 16; off; off >>= 1) s += __shfl_down_sync(0xffffffffu, s, off);
    if (lane == 0) out[w] = s;
}
__global__ void final_k(float* __restrict__ dout, const int* __restrict__ target) {
    __shared__ float sm[1024], ss[1024];
    int t = threadIdx.x;
    float m = -1e30f, s = 0.f;
    for (int j = t; j < P; j += 1024) {
        float x = dout[1 + j];
        float nm = fmaxf(m, x);
        s = s * expf(m - nm) + expf(x - nm);
        m = nm;
    }
    sm[t] = m; ss[t] = s; __syncthreads();
    for (int st = 512; st; st >>= 1) {
        if (t < st) {
            float m2 = sm[t + st], s2 = ss[t + st];
            float nm = fmaxf(sm[t], m2);
            ss[t] = ss[t] * expf(sm[t] - nm) + s2 * expf(m2 - nm);
            sm[t] = nm;
        }
        __syncthreads();
    }
    if (t == 0) {
        float lse = sm[0] + logf(ss[0]);
        dout[0] = (lse - dout[1 + (*target)]) + g_loss;
    }
}

// ---------------- host orchestration ----------------
static inline dim3 ew(int n) { return dim3((n + 255) / 256); }

#define GSYM(p, s) do { void* _q = nullptr; cudaGetSymbolAddress(&_q, s); p = (float*)_q; } while (0)

static float *s_part;

static void gemm128(const float* A, const float* B, float* C, int M, int K, int S,
                    float alpha, bool accum)
{
    int Kc = (((K + S - 1) / S) + 15) & ~15;
    dim3 g(S, (M + 127) / 128);
    gemm_n128_k<<<g, 256>>>(A, B, s_part, M, K, Kc);
    comb_n128_k<<<ew(M * 128), 256>>>(s_part, S, C, M, alpha, accum ? 1 : 0);
}

static void run_nce(const float* Z1, const float* Z2, int M,
                    float* rp, float* cp, float* lr, float* lc, float* dg)
{
    int nt = (M + 127) / 128;
    dim3 g(nt, nt);
    nce_fused_k<<<g, 256>>>(Z1, Z2, M, rp, cp);
    lse_comb_k<<<ew(M), 256>>>(rp, nt, lr, M);
    lse_comb_k<<<ew(M), 256>>>(cp, nt, lc, M);
    diag_k<<<(M * 32 + 255) / 256, 256>>>(Z1, Z2, M, dg);
    nce_accum_k<<<1, 256>>>(lr, lc, dg, M);
}

extern "C" void kernel_launch(void* const* d_in, const int* in_sizes, int n_in,
                              void* d_out, int out_size)
{
    const float* poi_w    = (const float*)d_in[0];
    const float* ui_w     = (const float*)d_in[1];
    const float* w_gc     = (const float*)d_in[2];
    const float* b_gc     = (const float*)d_in[3];
    const float* w_gU     = (const float*)d_in[4];
    const float* b_gU     = (const float*)d_in[5];
    const float* cheb_r   = (const float*)d_in[6];
    const float* cheb_i   = (const float*)d_in[7];
    const float* HG_pu    = (const float*)d_in[8];
    const float* HG_up    = (const float*)d_in[9];
    const float* U_I      = (const float*)d_in[10];
    const float* noise1   = (const float*)d_in[11];
    const float* noise2   = (const float*)d_in[12];
    const int*   target   = (const int*)d_in[13];
    const int*   user_col = (const int*)d_in[14];
    const int*   user_ui  = (const int*)d_in[15];
    float* out = (float*)d_out;

    float *A, *B, *C2, *acc, *hg, *z2a, *uA, *uB, *uC, *uacc, *ue, *z2b;
    float *hus, *ucl, *X1r, *X1i, *X2r, *X2i, *Tr, *Ti, *Gr, *Gi, *fr, *fi, *fp;
    float *lr, *lc, *dg, *tabc, *tabs, *CrP, *CiP, *br, *bi, *rp, *cp;
    GSYM(A, g_A); GSYM(B, g_B); GSYM(C2, g_C2); GSYM(acc, g_acc);
    GSYM(hg, g_hg); GSYM(z2a, g_z2a);
    GSYM(uA, g_uA); GSYM(uB, g_uB); GSYM(uC, g_uC); GSYM(uacc, g_uacc);
    GSYM(ue, g_ue); GSYM(z2b, g_z2b);
    GSYM(hus, g_hus); GSYM(ucl, g_ucl);
    GSYM(X1r, g_X1r); GSYM(X1i, g_X1i); GSYM(X2r, g_X2r); GSYM(X2i, g_X2i);
    GSYM(Tr, g_Tr); GSYM(Ti, g_Ti); GSYM(Gr, g_Gr); GSYM(Gi, g_Gi);
    GSYM(fr, g_fr); GSYM(fi, g_fi); GSYM(fp, g_fp);
    GSYM(lr, g_lr); GSYM(lc, g_lc); GSYM(dg, g_dg);
    GSYM(tabc, g_tabc); GSYM(tabs, g_tabs); GSYM(CrP, g_CrP); GSYM(CiP, g_CiP);
    GSYM(br, g_br); GSYM(bi, g_bi); GSYM(rp, g_rp); GSYM(cp, g_cp);
    GSYM(s_part, g_part);

    // setup (also zeroes loss accumulator)
    setup_tab_k<<<ew(D * D), 256>>>();
    pack_cheb_k<<<ew(CW * D), 256>>>(cheb_r, cheb_i);
    bias_k<<<1, 128>>>(cheb_r, cheb_i);

    // gated embeddings
    gemm128(poi_w, w_gc, B, P, 128, 4, 1.f, false);
    gate_k<<<ew(P * D), 256>>>(poi_w, B, b_gc, A, P * D);
    gemm128(ui_w, w_gU, uB, NU, 128, 4, 1.f, false);
    gate_k<<<ew(NU * D), 256>>>(ui_w, uB, b_gU, uA, NU * D);

    // hconv (2 layers) -> hg
    copy_k<<<ew(P * D), 256>>>(acc, A, P * D);
    skinny_mm_k<<<NHE, 512>>>(HG_pu, A, hus, P);
    { dim3 g(2, 128); sgemm_kernel<<<g, 256>>>(HG_up, hus, B, P, 128, NHE, 1.f, 0, 0); }
    add_k<<<ew(P * D), 256>>>(acc, B, P * D);
    skinny_mm_k<<<NHE, 512>>>(HG_pu, B, hus, P);
    { dim3 g(2, 128); sgemm_kernel<<<g, 256>>>(HG_up, hus, C2, P, 128, NHE, 1.f, 0, 0); }
    add_k<<<ew(P * D), 256>>>(acc, C2, P * D);
    l2norm_k<<<P, 128>>>(acc, hg);
    addnorm_k<<<P, 128>>>(hg, noise1, z2a);

    // level_loss = info_nce(hg, hg+noise1)
    run_nce(hg, z2a, P, rp, cp, lr, lc, dg);

    // hg_users
    skinny_mm_k<<<NHE, 512>>>(HG_pu, hg, hus, P);

    // gconv (2 layers) -> ue
    copy_k<<<ew(NU * D), 256>>>(uacc, uA, NU * D);
    gemm128(U_I, uA, uB, NU, NU, 8, 1.f, false);
    add_k<<<ew(NU * D), 256>>>(uacc, uB, NU * D);
    gemm128(U_I, uB, uC, NU, NU, 8, 1.f, false);
    add_k<<<ew(NU * D), 256>>>(uacc, uC, NU * D);
    l2norm_k<<<NU, 128>>>(uacc, ue);
    addnorm_k<<<NU, 128>>>(ue, noise2, z2b);

    // level_loss1 = info_nce(ue, ue+noise2)
    run_nce(ue, z2b, NU, rp, cp, lr, lc, dg);

    const float* poi_e = ue + (size_t)NUC * D;

    // ssl_p = info_nce(hg, poi_e)
    run_nce(hg, poi_e, P, rp, cp, lr, lc, dg);

    // ssl = info_nce(ue[0:42], l2norm(hg_users[9:]))  (small path)
    l2norm_k<<<NUC, 128>>>(hus + 9 * D, ucl);
    { dim3 g(1, 1); sgemm_kernel<<<g, 256>>>(ue, ucl, s_part, NUC, NUC, 128, 5.f, 1, 0); }
    row_lse_k<<<NUC, 128>>>(s_part, lr, dg, NUC);
    { dim3 g(1, 1); col_part_k<<<g, 256>>>(s_part, NUC, 1); }
    col_comb_k<<<1, 256>>>(lc, NUC, 1);
    nce_accum_k<<<1, 256>>>(lr, lc, dg, NUC);

    // gated KAN: DFT -> cheby gate -> IDFT
    gemm128(hg, tabc, X1r, P, 128, 4,  1.f, false);
    gemm128(hg, tabs, X1i, P, 128, 4, -1.f, false);
    gemm128(poi_e, tabc, X2r, P, 128, 4,  1.f, false);
    gemm128(poi_e, tabs, X2i, P, 128, 4, -1.f, false);
    buildT_k<<<ew(P * D), 256>>>(X1r, X2r, Tr, P * D);
    buildT_k<<<ew(P * D), 256>>>(X1i, X2i, Ti, P * D);
    gemm128(Tr, CrP, Gr, P, CW, 4, 1.f, false);
    gemm128(Ti, CiP, Gi, P, CW, 4, 1.f, false);
    kan_gate_k<<<ew(P * D), 256>>>(Gr, br, X1r, X2r, fr, P * D);
    kan_gate_k<<<ew(P * D), 256>>>(Gi, bi, X1i, X2i, fi, P * D);
    gemm128(fr, tabc, fp, P, 128, 4,  1.f / 128.f, false);
    gemm128(fi, tabs, fp, P, 128, 4, -1.f / 128.f, true);

    // final user vector, logits, loss
    finalu_k<<<1, 128>>>(user_ui, user_col);
    outvec_k<<<(P * 32 + 255) / 256, 256>>>(fp, out + 1);
    final_k<<<1, 1024>>>(out, target);
}

// round 5
// speedup vs baseline: 1.3675x; 1.0781x over previous
#include <cuda_runtime.h>
#include <math.h>

#define P    8192
#define D    128
#define NU   8234
#define NHE  51
#define NUC  42
#define CW   768
#define MPAD 8320
#define NT   65

typedef unsigned long long u64;

__device__ __forceinline__ u64 pack2(float lo, float hi) {
    u64 r; asm("mov.b64 %0,{%1,%2};" : "=l"(r) : "f"(lo), "f"(hi)); return r;
}
__device__ __forceinline__ void unpack2(u64 v, float& lo, float& hi) {
    asm("mov.b64 {%0,%1},%2;" : "=f"(lo), "=f"(hi) : "l"(v));
}
__device__ __forceinline__ void ffma2(u64& acc, u64 a, u64 b) {
    asm("fma.rn.f32x2 %0,%1,%2,%0;" : "+l"(acc) : "l"(a), "l"(b));
}

// ---------------- device scratch ----------------
__device__ float g_A[P*D];
__device__ float g_B[P*D];
__device__ float g_C2[P*D];
__device__ float g_acc[P*D];
__device__ float g_hg[P*D];
__device__ float g_z2a[P*D];
__device__ float g_uA[NU*D];
__device__ float g_uB[NU*D];
__device__ float g_uC[NU*D];
__device__ float g_uacc[NU*D];
__device__ float g_ue[NU*D];
__device__ float g_z2b[NU*D];
__device__ float g_hus[NHE*D];
__device__ float g_ucl[NUC*D];
__device__ float g_X1r[P*D], g_X1i[P*D], g_X2r[P*D], g_X2i[P*D];
__device__ float g_Tr[(size_t)P*CW], g_Ti[(size_t)P*CW];
__device__ float g_Gr[P*D], g_Gi[P*D];
__device__ float g_fr[P*D], g_fi[P*D];
__device__ float g_fp[P*D];
__device__ float g_part[(size_t)8*MPAD*128];
__device__ float g_rp[(size_t)NT*MPAD];
__device__ float g_cp[(size_t)NT*MPAD];
__device__ float g_lr[NU], g_lc[NU], g_dg[NU];
__device__ float g_psum[8*NU];
__device__ float g_tabc[D*D], g_tabs[D*D];
__device__ float g_CrP[CW*D], g_CiP[CW*D];
__device__ float g_br[D], g_bi[D];
__device__ float g_fu[D];
__device__ float g_loss;

// =====================================================================
// Fused InfoNCE, double-buffered + f32x2 packed FMA.
// sim = 5*Z1@Z2^T (K=128), exp(sim-5), per-tile row/col partial sums.
// grid (nt,nt), 256 thr, 128x128 tile, 8x8 microtile.
// =====================================================================
__global__ __launch_bounds__(256, 2)
void nce_fused_k(const float* __restrict__ Z1, const float* __restrict__ Z2,
                 int M, float* __restrict__ rowp, float* __restrict__ colp)
{
    __shared__ __align__(16) float As[2][16][132];
    __shared__ __align__(16) float Bs[2][16][132];
    __shared__ __align__(16) float red[128][17];

    int bm = blockIdx.y * 128, bn = blockIdx.x * 128;
    int t = threadIdx.x, tx = t & 15, ty = t >> 4;
    u64 acc2[8][4];
    #pragma unroll
    for (int i = 0; i < 8; i++)
        #pragma unroll
        for (int j = 0; j < 4; j++) acc2[i][j] = 0ULL;

    float4 ra[2], rb[2];

    #pragma unroll
    for (int i = 0; i < 2; i++) {
        int f = t + i * 256, row = f >> 2, c4 = (f & 3) * 4;
        int gm = bm + row;
        ra[i] = (gm < M) ? *(const float4*)&Z1[(size_t)gm * 128 + c4]
                         : make_float4(0.f, 0.f, 0.f, 0.f);
        int gn = bn + row;
        rb[i] = (gn < M) ? *(const float4*)&Z2[(size_t)gn * 128 + c4]
                         : make_float4(0.f, 0.f, 0.f, 0.f);
    }
    #pragma unroll
    for (int i = 0; i < 2; i++) {
        int f = t + i * 256, row = f >> 2, c4 = (f & 3) * 4;
        As[0][c4 + 0][row] = ra[i].x; As[0][c4 + 1][row] = ra[i].y;
        As[0][c4 + 2][row] = ra[i].z; As[0][c4 + 3][row] = ra[i].w;
        Bs[0][c4 + 0][row] = rb[i].x; Bs[0][c4 + 1][row] = rb[i].y;
        Bs[0][c4 + 2][row] = rb[i].z; Bs[0][c4 + 3][row] = rb[i].w;
    }
    __syncthreads();

    #pragma unroll 1
    for (int kt = 0; kt < 8; kt++) {
        int cur = kt & 1;
        if (kt < 7) {
            int k0 = (kt + 1) * 16;
            #pragma unroll
            for (int i = 0; i < 2; i++) {
                int f = t + i * 256, row = f >> 2, c4 = (f & 3) * 4;
                int gm = bm + row;
                ra[i] = (gm < M) ? *(const float4*)&Z1[(size_t)gm * 128 + k0 + c4]
                                 : make_float4(0.f, 0.f, 0.f, 0.f);
                int gn = bn + row;
                rb[i] = (gn < M) ? *(const float4*)&Z2[(size_t)gn * 128 + k0 + c4]
                                 : make_float4(0.f, 0.f, 0.f, 0.f);
            }
        }
        #pragma unroll
        for (int kk = 0; kk < 16; kk++) {
            float a[8];
            *(float4*)&a[0] = *(const float4*)&As[cur][kk][ty * 8];
            *(float4*)&a[4] = *(const float4*)&As[cur][kk][ty * 8 + 4];
            double2 b01 = *(const double2*)&Bs[cur][kk][tx * 8];
            double2 b23 = *(const double2*)&Bs[cur][kk][tx * 8 + 4];
            u64 b2[4] = { __double_as_longlong(b01.x), __double_as_longlong(b01.y),
                          __double_as_longlong(b23.x), __double_as_longlong(b23.y) };
            #pragma unroll
            for (int i = 0; i < 8; i++) {
                u64 ai = pack2(a[i], a[i]);
                ffma2(acc2[i][0], ai, b2[0]);
                ffma2(acc2[i][1], ai, b2[1]);
                ffma2(acc2[i][2], ai, b2[2]);
                ffma2(acc2[i][3], ai, b2[3]);
            }
        }
        if (kt < 7) {
            int nb = 1 - cur;
            #pragma unroll
            for (int i = 0; i < 2; i++) {
                int f = t + i * 256, row = f >> 2, c4 = (f & 3) * 4;
                As[nb][c4 + 0][row] = ra[i].x; As[nb][c4 + 1][row] = ra[i].y;
                As[nb][c4 + 2][row] = ra[i].z; As[nb][c4 + 3][row] = ra[i].w;
                Bs[nb][c4 + 0][row] = rb[i].x; Bs[nb][c4 + 1][row] = rb[i].y;
                Bs[nb][c4 + 2][row] = rb[i].z; Bs[nb][c4 + 3][row] = rb[i].w;
            }
            __syncthreads();
        }
    }

    // epilogue: exp + row/col partial sums
    float rs[8], cs[8];
    #pragma unroll
    for (int i = 0; i < 8; i++) { rs[i] = 0.f; cs[i] = 0.f; }
    #pragma unroll
    for (int i = 0; i < 8; i++) {
        int gm = bm + ty * 8 + i;
        #pragma unroll
        for (int jp = 0; jp < 4; jp++) {
            float c0, c1;
            unpack2(acc2[i][jp], c0, c1);
            int gn0 = bn + tx * 8 + jp * 2, gn1 = gn0 + 1;
            float e0 = (gm < M && gn0 < M) ? __expf(c0 * 5.f - 5.f) : 0.f;
            float e1 = (gm < M && gn1 < M) ? __expf(c1 * 5.f - 5.f) : 0.f;
            rs[i] += e0 + e1;
            cs[jp * 2] += e0; cs[jp * 2 + 1] += e1;
        }
    }
    __syncthreads();
    #pragma unroll
    for (int i = 0; i < 8; i++) red[ty * 8 + i][tx] = rs[i];
    __syncthreads();
    if (t < 128) {
        float s = 0.f;
        #pragma unroll
        for (int q = 0; q < 16; q++) s += red[t][q];
        rowp[(size_t)blockIdx.x * MPAD + bm + t] = s;
    }
    __syncthreads();
    #pragma unroll
    for (int j = 0; j < 8; j++) red[tx * 8 + j][ty] = cs[j];
    __syncthreads();
    if (t < 128) {
        float s = 0.f;
        #pragma unroll
        for (int q = 0; q < 16; q++) s += red[t][q];
        colp[(size_t)blockIdx.y * MPAD + bn + t] = s;
    }
}

__global__ void lse_comb_k(const float* __restrict__ pp, int ntiles,
                           float* __restrict__ lse, int M)
{
    int r = blockIdx.x * 256 + threadIdx.x;
    if (r >= M) return;
    float s = 0.f;
    for (int q = 0; q < ntiles; q++) s += pp[(size_t)q * MPAD + r];
    lse[r] = 5.f + logf(s);
}

__global__ void diag_k(const float* __restrict__ Z1, const float* __restrict__ Z2,
                       int M, float* __restrict__ dg)
{
    int gt = blockIdx.x * blockDim.x + threadIdx.x;
    int r = gt >> 5, lane = gt & 31;
    if (r >= M) return;
    const float* a = Z1 + (size_t)r * 128;
    const float* b = Z2 + (size_t)r * 128;
    float s = 0.f;
    #pragma unroll
    for (int d = lane; d < 128; d += 32) s += a[d] * b[d];
    #pragma unroll
    for (int off = 16; off; off >>= 1) s += __shfl_down_sync(0xffffffffu, s, off);
    if (lane == 0) dg[r] = 5.f * s;
}

// =====================================================================
// Double-buffered split-K GEMM + f32x2, N=128: Cp[s] = A(MxK)@B(Kx128).
// grid (S, mtiles), 256 threads, 128x128 tile, 8x8 microtile, BK=16.
// =====================================================================
__global__ __launch_bounds__(256, 2)
void gemm_n128_k(const float* __restrict__ A, const float* __restrict__ B,
                 float* __restrict__ Cp, int M, int K, int Kc)
{
    __shared__ __align__(16) float As[2][16][132];
    __shared__ __align__(16) float Bs[2][16][132];
    int s = blockIdx.x, bm = blockIdx.y * 128;
    int kb = s * Kc;
    int ke = min(K, kb + Kc);
    int nt = (ke > kb) ? (ke - kb + 15) / 16 : 0;
    int t = threadIdx.x, tx = t & 15, ty = t >> 4;
    u64 acc2[8][4];
    #pragma unroll
    for (int i = 0; i < 8; i++)
        #pragma unroll
        for (int j = 0; j < 4; j++) acc2[i][j] = 0ULL;

    float2 ra[4];
    float4 rb[2];

    if (nt > 0) {
        int k0 = kb, klen = min(16, ke - k0);
        #pragma unroll
        for (int i = 0; i < 4; i++) {
            int f = t + i * 256, row = f >> 3, c2 = (f & 7) * 2;
            int gm = bm + row;
            float2 v = make_float2(0.f, 0.f);
            if (gm < M) {
                if (c2 + 1 < klen)  v = *(const float2*)&A[(size_t)gm * K + k0 + c2];
                else if (c2 < klen) v.x = A[(size_t)gm * K + k0 + c2];
            }
            As[0][c2][row] = v.x; As[0][c2 + 1][row] = v.y;
        }
        #pragma unroll
        for (int i = 0; i < 2; i++) {
            int f = t + i * 256, kk = f >> 5, c4 = (f & 31) * 4;
            float4 v = (kk < klen) ? *(const float4*)&B[(size_t)(k0 + kk) * 128 + c4]
                                   : make_float4(0.f, 0.f, 0.f, 0.f);
            *(float4*)&Bs[0][kk][c4] = v;
        }
        __syncthreads();
    }

    for (int kt = 0; kt < nt; kt++) {
        int cur = kt & 1;
        if (kt + 1 < nt) {
            int k0 = kb + (kt + 1) * 16, klen = min(16, ke - k0);
            #pragma unroll
            for (int i = 0; i < 4; i++) {
                int f = t + i * 256, row = f >> 3, c2 = (f & 7) * 2;
                int gm = bm + row;
                float2 v = make_float2(0.f, 0.f);
                if (gm < M) {
                    if (c2 + 1 < klen)  v = *(const float2*)&A[(size_t)gm * K + k0 + c2];
                    else if (c2 < klen) v.x = A[(size_t)gm * K + k0 + c2];
                }
                ra[i] = v;
            }
            #pragma unroll
            for (int i = 0; i < 2; i++) {
                int f = t + i * 256, kk = f >> 5, c4 = (f & 31) * 4;
                rb[i] = (kk < klen) ? *(const float4*)&B[(size_t)(k0 + kk) * 128 + c4]
                                    : make_float4(0.f, 0.f, 0.f, 0.f);
            }
        }
        #pragma unroll
        for (int kk = 0; kk < 16; kk++) {
            float a[8];
            *(float4*)&a[0] = *(const float4*)&As[cur][kk][ty * 8];
            *(float4*)&a[4] = *(const float4*)&As[cur][kk][ty * 8 + 4];
            double2 b01 = *(const double2*)&Bs[cur][kk][tx * 8];
            double2 b23 = *(const double2*)&Bs[cur][kk][tx * 8 + 4];
            u64 b2[4] = { __double_as_longlong(b01.x), __double_as_longlong(b01.y),
                          __double_as_longlong(b23.x), __double_as_longlong(b23.y) };
            #pragma unroll
            for (int i = 0; i < 8; i++) {
                u64 ai = pack2(a[i], a[i]);
                ffma2(acc2[i][0], ai, b2[0]);
                ffma2(acc2[i][1], ai, b2[1]);
                ffma2(acc2[i][2], ai, b2[2]);
                ffma2(acc2[i][3], ai, b2[3]);
            }
        }
        if (kt + 1 < nt) {
            int nb = 1 - cur;
            #pragma unroll
            for (int i = 0; i < 4; i++) {
                int f = t + i * 256, row = f >> 3, c2 = (f & 7) * 2;
                As[nb][c2][row] = ra[i].x; As[nb][c2 + 1][row] = ra[i].y;
            }
            #pragma unroll
            for (int i = 0; i < 2; i++) {
                int f = t + i * 256, kk = f >> 5, c4 = (f & 31) * 4;
                *(float4*)&Bs[nb][kk][c4] = rb[i];
            }
            __syncthreads();
        }
    }

    size_t base = (size_t)s * ((size_t)MPAD * 128);
    #pragma unroll
    for (int i = 0; i < 8; i++) {
        int gm = bm + ty * 8 + i;
        if (gm >= M) continue;
        float c[8];
        #pragma unroll
        for (int jp = 0; jp < 4; jp++) unpack2(acc2[i][jp], c[jp * 2], c[jp * 2 + 1]);
        *(float4*)&Cp[base + (size_t)gm * 128 + tx * 8]     = *(float4*)&c[0];
        *(float4*)&Cp[base + (size_t)gm * 128 + tx * 8 + 4] = *(float4*)&c[4];
    }
}

__global__ void comb_n128_k(const float* __restrict__ Cp, int S,
                            float* __restrict__ C, int M, float alpha, int accum)
{
    int i = blockIdx.x * 256 + threadIdx.x;
    if (i >= M * 128) return;
    float s = 0.f;
    for (int q = 0; q < S; q++) s += Cp[(size_t)q * ((size_t)MPAD * 128) + i];
    float v = alpha * s;
    C[i] = accum ? C[i] + v : v;
}

// =====================================================================
// generic FFMA SGEMM (small cases: K=51 hconv, 42x42 NCE)
// =====================================================================
__global__ void sgemm_kernel(const float* __restrict__ A, const float* __restrict__ B,
                             float* __restrict__ C, int M, int N, int K,
                             float alpha, int transB, int accum)
{
    __shared__ __align__(16) float As[16][68];
    __shared__ __align__(16) float Bs[16][68];
    int bm = blockIdx.y * 64, bn = blockIdx.x * 64;
    int t  = threadIdx.x;
    int ty = t >> 4, tx = t & 15;
    float acc[4][4];
    #pragma unroll
    for (int i = 0; i < 4; i++)
        #pragma unroll
        for (int j = 0; j < 4; j++) acc[i][j] = 0.f;

    for (int k0 = 0; k0 < K; k0 += 16) {
        #pragma unroll
        for (int i = 0; i < 4; i++) {
            int e  = t + i * 256;
            int mm = e >> 4, kk = e & 15;
            int gm = bm + mm, gk = k0 + kk;
            As[kk][mm] = (gm < M && gk < K) ? A[(size_t)gm * K + gk] : 0.f;
        }
        if (!transB) {
            #pragma unroll
            for (int i = 0; i < 4; i++) {
                int e  = t + i * 256;
                int kk = e >> 6, nn = e & 63;
                int gk = k0 + kk, gn = bn + nn;
                Bs[kk][nn] = (gk < K && gn < N) ? B[(size_t)gk * N + gn] : 0.f;
            }
        } else {
            #pragma unroll
            for (int i = 0; i < 4; i++) {
                int e  = t + i * 256;
                int nn = e >> 4, kk = e & 15;
                int gn = bn + nn, gk = k0 + kk;
                Bs[kk][nn] = (gn < N && gk < K) ? B[(size_t)gn * K + gk] : 0.f;
            }
        }
        __syncthreads();
        #pragma unroll
        for (int kk = 0; kk < 16; kk++) {
            float4 av = *(const float4*)&As[kk][ty * 4];
            float4 bv = *(const float4*)&Bs[kk][tx * 4];
            float a4[4] = {av.x, av.y, av.z, av.w};
            float b4[4] = {bv.x, bv.y, bv.z, bv.w};
            #pragma unroll
            for (int i = 0; i < 4; i++)
                #pragma unroll
                for (int j = 0; j < 4; j++) acc[i][j] += a4[i] * b4[j];
        }
        __syncthreads();
    }
    #pragma unroll
    for (int i = 0; i < 4; i++) {
        int gm = bm + ty * 4 + i;
        if (gm >= M) continue;
        #pragma unroll
        for (int j = 0; j < 4; j++) {
            int gn = bn + tx * 4 + j;
            if (gn >= N) continue;
            size_t idx = (size_t)gm * N + gn;
            float v = alpha * acc[i][j];
            C[idx] = accum ? (C[idx] + v) : v;
        }
    }
}

// ---- tall-skinny: C(NHE x 128) = A(NHE x K) @ B(K x 128) ----
__global__ void skinny_mm_k(const float* __restrict__ A, const float* __restrict__ B,
                            float* __restrict__ C, int K)
{
    int m = blockIdx.x;
    int t = threadIdx.x;
    int n = t & 127;
    int q = t >> 7;
    const float* a = A + (size_t)m * K;
    float s0 = 0.f, s1 = 0.f;
    for (int k = q; k < K; k += 8) {
        s0 += a[k] * B[(size_t)k * 128 + n];
        int k2 = k + 4;
        if (k2 < K) s1 += a[k2] * B[(size_t)k2 * 128 + n];
    }
    __shared__ float sh[3][128];
    float s = s0 + s1;
    if (q) sh[q - 1][n] = s;
    __syncthreads();
    if (q == 0) C[(size_t)m * 128 + n] = s + sh[0][n] + sh[1][n] + sh[2][n];
}

// ---------------- elementwise ----------------
__global__ void copy_k(float* d, const float* s, int n) {
    int i = blockIdx.x * blockDim.x + threadIdx.x;
    if (i < n) d[i] = s[i];
}
__global__ void add_k(float* d, const float* s, int n) {
    int i = blockIdx.x * blockDim.x + threadIdx.x;
    if (i < n) d[i] += s[i];
}
__global__ void gate_k(const float* __restrict__ w, const float* __restrict__ tm,
                       const float* __restrict__ b, float* __restrict__ out, int n) {
    int i = blockIdx.x * blockDim.x + threadIdx.x;
    if (i >= n) return;
    float z = tm[i] + b[i & 127];
    out[i] = w[i] / (1.f + expf(-z));
}
__global__ void kan_gate_k(const float* __restrict__ G, const float* __restrict__ bias,
                           const float* __restrict__ Xa, const float* __restrict__ Xb,
                           float* __restrict__ f, int n) {
    int i = blockIdx.x * blockDim.x + threadIdx.x;
    if (i >= n) return;
    float g = 1.f / (1.f + expf(-(G[i] + bias[i & 127])));
    f[i] = g * Xa[i] + (1.f - g) * Xb[i];
}
__global__ void buildT_k(const float* __restrict__ Xa, const float* __restrict__ Xb,
                         float* __restrict__ T, int n) {
    int i = blockIdx.x * blockDim.x + threadIdx.x;
    if (i >= n) return;
    int row = i >> 7, c = i & 127;
    float x  = tanhf(Xa[i]);
    float t2 = 2.f * x * x - 1.f;
    float t3 = 2.f * x * t2 - x;
    float* p = T + (size_t)row * CW + c * 3;
    p[0] = x; p[1] = t2; p[2] = t3;
    x  = tanhf(Xb[i]);
    t2 = 2.f * x * x - 1.f;
    t3 = 2.f * x * t2 - x;
    p = T + (size_t)row * CW + 384 + c * 3;
    p[0] = x; p[1] = t2; p[2] = t3;
}

// ---------------- L2 normalize ----------------
__global__ void l2norm_k(const float* __restrict__ x, float* __restrict__ y) {
    int r = blockIdx.x, t = threadIdx.x;
    float v = x[(size_t)r * 128 + t];
    __shared__ float sh[128];
    sh[t] = v * v; __syncthreads();
    for (int st = 64; st; st >>= 1) { if (t < st) sh[t] += sh[t + st]; __syncthreads(); }
    y[(size_t)r * 128 + t] = v / fmaxf(sqrtf(sh[0]), 1e-12f);
}
__global__ void addnorm_k(const float* __restrict__ x, const float* __restrict__ ns,
                          float* __restrict__ y) {
    int r = blockIdx.x, t = threadIdx.x;
    float v = x[(size_t)r * 128 + t] + ns[(size_t)r * 128 + t];
    __shared__ float sh[128];
    sh[t] = v * v; __syncthreads();
    for (int st = 64; st; st >>= 1) { if (t < st) sh[t] += sh[t + st]; __syncthreads(); }
    y[(size_t)r * 128 + t] = v / fmaxf(sqrtf(sh[0]), 1e-12f);
}

// ---------------- small InfoNCE path (NUC only) ----------------
__global__ void row_lse_k(const float* __restrict__ S, float* lse, float* diag, int M) {
    int r = blockIdx.x, t = threadIdx.x;
    const float* row = S + (size_t)r * M;
    float s = 0.f;
    for (int j = t; j < M; j += 128) s += expf(row[j] - 5.0f);
    __shared__ float sh[128];
    sh[t] = s; __syncthreads();
    for (int st = 64; st; st >>= 1) { if (t < st) sh[t] += sh[t + st]; __syncthreads(); }
    if (t == 0) { lse[r] = 5.0f + logf(sh[0]); diag[r] = row[r]; }
}
__global__ void col_part_k(const float* __restrict__ S, int M, int splits) {
    int col = blockIdx.x * 256 + threadIdx.x;
    if (col >= M) return;
    int sp = blockIdx.y;
    long r0 = (long)M * sp / splits, r1 = (long)M * (sp + 1) / splits;
    float s = 0.f;
    for (long r = r0; r < r1; r++) s += expf(S[(size_t)r * M + col] - 5.0f);
    g_psum[sp * NU + col] = s;
}
__global__ void col_comb_k(float* lsec, int M, int splits) {
    int col = blockIdx.x * 256 + threadIdx.x;
    if (col >= M) return;
    float s = 0.f;
    for (int sp = 0; sp < splits; sp++) s += g_psum[sp * NU + col];
    lsec[col] = 5.0f + logf(s);
}
__global__ void nce_accum_k(const float* lr, const float* lc, const float* dg, int M) {
    __shared__ float sh[256];
    int t = threadIdx.x;
    float a = 0.f;
    for (int i = t; i < M; i += 256) a += (lr[i] - dg[i]) + (lc[i] - dg[i]);
    sh[t] = a; __syncthreads();
    for (int st = 128; st; st >>= 1) { if (t < st) sh[t] += sh[t + st]; __syncthreads(); }
    if (t == 0) g_loss += 0.5f * sh[0] / (float)M;
}

// ---------------- setup ----------------
__global__ void setup_tab_k() {
    int i = blockIdx.x * blockDim.x + threadIdx.x;
    if (i >= D * D) return;
    int a = i >> 7, b = i & 127;
    float ang = 6.28318530717958647692f * (float)((a * b) & 127) / 128.f;
    g_tabc[i] = cosf(ang);
    g_tabs[i] = sinf(ang);
}
__global__ void pack_cheb_k(const float* __restrict__ cr, const float* __restrict__ ci) {
    int i = blockIdx.x * blockDim.x + threadIdx.x;
    if (i >= CW * D) return;
    int r = i >> 7, o = i & 127;
    int rr = r % 384;
    int ii = rr / 3, k = rr % 3 + 1;
    g_CrP[i] = cr[((size_t)ii * 128 + o) * 4 + k];
    g_CiP[i] = ci[((size_t)ii * 128 + o) * 4 + k];
}
__global__ void bias_k(const float* __restrict__ cr, const float* __restrict__ ci) {
    int o = threadIdx.x;
    float s1 = 0.f, s2 = 0.f;
    for (int ii = 0; ii < 128; ii++) {
        s1 += cr[((size_t)ii * 128 + o) * 4];
        s2 += ci[((size_t)ii * 128 + o) * 4];
    }
    g_br[o] = 2.f * s1;
    g_bi[o] = 2.f * s2;
    if (o == 0) g_loss = 0.f;
}

// ---------------- finals ----------------
__global__ void finalu_k(const int* __restrict__ uui, const int* __restrict__ ucol) {
    int d = threadIdx.x;
    g_fu[d] = g_ue[(size_t)(*uui) * 128 + d] + g_hus[(size_t)(*ucol) * 128 + d];
}
__global__ void outvec_k(const float* __restrict__ fp, float* __restrict__ out) {
    int gt = blockIdx.x * blockDim.x + threadIdx.x;
    int w = gt >> 5, lane = gt & 31;
    if (w >= P) return;
    const float* row = fp + (size_t)w * 128;
    float s = 0.f;
    #pragma unroll
    for (int d = lane; d < 128; d += 32) s += row[d] * g_fu[d];
    #pragma unroll
    for (int off = 16; off; off >>= 1) s += __shfl_down_sync(0xffffffffu, s, off);
    if (lane == 0) out[w] = s;
}
__global__ void final_k(float* __restrict__ dout, const int* __restrict__ target) {
    __shared__ float sm[1024], ss[1024];
    int t = threadIdx.x;
    float m = -1e30f, s = 0.f;
    for (int j = t; j < P; j += 1024) {
        float x = dout[1 + j];
        float nm = fmaxf(m, x);
        s = s * expf(m - nm) + expf(x - nm);
        m = nm;
    }
    sm[t] = m; ss[t] = s; __syncthreads();
    for (int st = 512; st; st >>= 1) {
        if (t < st) {
            float m2 = sm[t + st], s2 = ss[t + st];
            float nm = fmaxf(sm[t], m2);
            ss[t] = ss[t] * expf(sm[t] - nm) + s2 * expf(m2 - nm);
            sm[t] = nm;
        }
        __syncthreads();
    }
    if (t == 0) {
        float lse = sm[0] + logf(ss[0]);
        dout[0] = (lse - dout[1 + (*target)]) + g_loss;
    }
}

// ---------------- host orchestration ----------------
static inline dim3 ew(int n) { return dim3((n + 255) / 256); }

#define GSYM(p, s) do { void* _q = nullptr; cudaGetSymbolAddress(&_q, s); p = (float*)_q; } while (0)

static float *s_part;

static void gemm128(const float* A, const float* B, float* C, int M, int K, int S,
                    float alpha, bool accum)
{
    int Kc = (((K + S - 1) / S) + 15) & ~15;
    dim3 g(S, (M + 127) / 128);
    gemm_n128_k<<<g, 256>>>(A, B, s_part, M, K, Kc);
    comb_n128_k<<<ew(M * 128), 256>>>(s_part, S, C, M, alpha, accum ? 1 : 0);
}

static void run_nce(const float* Z1, const float* Z2, int M,
                    float* rp, float* cp, float* lr, float* lc, float* dg)
{
    int nt = (M + 127) / 128;
    dim3 g(nt, nt);
    nce_fused_k<<<g, 256>>>(Z1, Z2, M, rp, cp);
    lse_comb_k<<<ew(M), 256>>>(rp, nt, lr, M);
    lse_comb_k<<<ew(M), 256>>>(cp, nt, lc, M);
    diag_k<<<(M * 32 + 255) / 256, 256>>>(Z1, Z2, M, dg);
    nce_accum_k<<<1, 256>>>(lr, lc, dg, M);
}

extern "C" void kernel_launch(void* const* d_in, const int* in_sizes, int n_in,
                              void* d_out, int out_size)
{
    const float* poi_w    = (const float*)d_in[0];
    const float* ui_w     = (const float*)d_in[1];
    const float* w_gc     = (const float*)d_in[2];
    const float* b_gc     = (const float*)d_in[3];
    const float* w_gU     = (const float*)d_in[4];
    const float* b_gU     = (const float*)d_in[5];
    const float* cheb_r   = (const float*)d_in[6];
    const float* cheb_i   = (const float*)d_in[7];
    const float* HG_pu    = (const float*)d_in[8];
    const float* HG_up    = (const float*)d_in[9];
    const float* U_I      = (const float*)d_in[10];
    const float* noise1   = (const float*)d_in[11];
    const float* noise2   = (const float*)d_in[12];
    const int*   target   = (const int*)d_in[13];
    const int*   user_col = (const int*)d_in[14];
    const int*   user_ui  = (const int*)d_in[15];
    float* out = (float*)d_out;

    float *A, *B, *C2, *acc, *hg, *z2a, *uA, *uB, *uC, *uacc, *ue, *z2b;
    float *hus, *ucl, *X1r, *X1i, *X2r, *X2i, *Tr, *Ti, *Gr, *Gi, *fr, *fi, *fp;
    float *lr, *lc, *dg, *tabc, *tabs, *CrP, *CiP, *br, *bi, *rp, *cp;
    GSYM(A, g_A); GSYM(B, g_B); GSYM(C2, g_C2); GSYM(acc, g_acc);
    GSYM(hg, g_hg); GSYM(z2a, g_z2a);
    GSYM(uA, g_uA); GSYM(uB, g_uB); GSYM(uC, g_uC); GSYM(uacc, g_uacc);
    GSYM(ue, g_ue); GSYM(z2b, g_z2b);
    GSYM(hus, g_hus); GSYM(ucl, g_ucl);
    GSYM(X1r, g_X1r); GSYM(X1i, g_X1i); GSYM(X2r, g_X2r); GSYM(X2i, g_X2i);
    GSYM(Tr, g_Tr); GSYM(Ti, g_Ti); GSYM(Gr, g_Gr); GSYM(Gi, g_Gi);
    GSYM(fr, g_fr); GSYM(fi, g_fi); GSYM(fp, g_fp);
    GSYM(lr, g_lr); GSYM(lc, g_lc); GSYM(dg, g_dg);
    GSYM(tabc, g_tabc); GSYM(tabs, g_tabs); GSYM(CrP, g_CrP); GSYM(CiP, g_CiP);
    GSYM(br, g_br); GSYM(bi, g_bi); GSYM(rp, g_rp); GSYM(cp, g_cp);
    GSYM(s_part, g_part);

    // setup (also zeroes loss accumulator)
    setup_tab_k<<<ew(D * D), 256>>>();
    pack_cheb_k<<<ew(CW * D), 256>>>(cheb_r, cheb_i);
    bias_k<<<1, 128>>>(cheb_r, cheb_i);

    // gated embeddings
    gemm128(poi_w, w_gc, B, P, 128, 4, 1.f, false);
    gate_k<<<ew(P * D), 256>>>(poi_w, B, b_gc, A, P * D);
    gemm128(ui_w, w_gU, uB, NU, 128, 4, 1.f, false);
    gate_k<<<ew(NU * D), 256>>>(ui_w, uB, b_gU, uA, NU * D);

    // hconv (2 layers) -> hg
    copy_k<<<ew(P * D), 256>>>(acc, A, P * D);
    skinny_mm_k<<<NHE, 512>>>(HG_pu, A, hus, P);
    { dim3 g(2, 128); sgemm_kernel<<<g, 256>>>(HG_up, hus, B, P, 128, NHE, 1.f, 0, 0); }
    add_k<<<ew(P * D), 256>>>(acc, B, P * D);
    skinny_mm_k<<<NHE, 512>>>(HG_pu, B, hus, P);
    { dim3 g(2, 128); sgemm_kernel<<<g, 256>>>(HG_up, hus, C2, P, 128, NHE, 1.f, 0, 0); }
    add_k<<<ew(P * D), 256>>>(acc, C2, P * D);
    l2norm_k<<<P, 128>>>(acc, hg);
    addnorm_k<<<P, 128>>>(hg, noise1, z2a);

    // level_loss = info_nce(hg, hg+noise1)
    run_nce(hg, z2a, P, rp, cp, lr, lc, dg);

    // hg_users
    skinny_mm_k<<<NHE, 512>>>(HG_pu, hg, hus, P);

    // gconv (2 layers) -> ue
    copy_k<<<ew(NU * D), 256>>>(uacc, uA, NU * D);
    gemm128(U_I, uA, uB, NU, NU, 8, 1.f, false);
    add_k<<<ew(NU * D), 256>>>(uacc, uB, NU * D);
    gemm128(U_I, uB, uC, NU, NU, 8, 1.f, false);
    add_k<<<ew(NU * D), 256>>>(uacc, uC, NU * D);
    l2norm_k<<<NU, 128>>>(uacc, ue);
    addnorm_k<<<NU, 128>>>(ue, noise2, z2b);

    // level_loss1 = info_nce(ue, ue+noise2)
    run_nce(ue, z2b, NU, rp, cp, lr, lc, dg);

    const float* poi_e = ue + (size_t)NUC * D;

    // ssl_p = info_nce(hg, poi_e)
    run_nce(hg, poi_e, P, rp, cp, lr, lc, dg);

    // ssl = info_nce(ue[0:42], l2norm(hg_users[9:]))  (small path)
    l2norm_k<<<NUC, 128>>>(hus + 9 * D, ucl);
    { dim3 g(1, 1); sgemm_kernel<<<g, 256>>>(ue, ucl, s_part, NUC, NUC, 128, 5.f, 1, 0); }
    row_lse_k<<<NUC, 128>>>(s_part, lr, dg, NUC);
    { dim3 g(1, 1); col_part_k<<<g, 256>>>(s_part, NUC, 1); }
    col_comb_k<<<1, 256>>>(lc, NUC, 1);
    nce_accum_k<<<1, 256>>>(lr, lc, dg, NUC);

    // gated KAN: DFT -> cheby gate -> IDFT
    gemm128(hg, tabc, X1r, P, 128, 4,  1.f, false);
    gemm128(hg, tabs, X1i, P, 128, 4, -1.f, false);
    gemm128(poi_e, tabc, X2r, P, 128, 4,  1.f, false);
    gemm128(poi_e, tabs, X2i, P, 128, 4, -1.f, false);
    buildT_k<<<ew(P * D), 256>>>(X1r, X2r, Tr, P * D);
    buildT_k<<<ew(P * D), 256>>>(X1i, X2i, Ti, P * D);
    gemm128(Tr, CrP, Gr, P, CW, 4, 1.f, false);
    gemm128(Ti, CiP, Gi, P, CW, 4, 1.f, false);
    kan_gate_k<<<ew(P * D), 256>>>(Gr, br, X1r, X2r, fr, P * D);
    kan_gate_k<<<ew(P * D), 256>>>(Gi, bi, X1i, X2i, fi, P * D);
    gemm128(fr, tabc, fp, P, 128, 4,  1.f / 128.f, false);
    gemm128(fi, tabs, fp, P, 128, 4, -1.f / 128.f, true);

    // final user vector, logits, loss
    finalu_k<<<1, 128>>>(user_ui, user_col);
    outvec_k<<<(P * 32 + 255) / 256, 256>>>(fp, out + 1);
    final_k<<<1, 1024>>>(out, target);
}

// round 7
// speedup vs baseline: 1.4115x; 1.0322x over previous
#include <cuda_runtime.h>
#include <math.h>

#define P    8192
#define D    128
#define NU   8234
#define NHE  51
#define NUC  42
#define CW   768
#define MPAD 8320
#define NT   65
#define ASTR 20          // padded A-row stride (floats), 16B-aligned

typedef unsigned long long u64;

__device__ __forceinline__ u64 pack2(float lo, float hi) {
    u64 r; asm("mov.b64 %0,{%1,%2};" : "=l"(r) : "f"(lo), "f"(hi)); return r;
}
__device__ __forceinline__ void unpack2(u64 v, float& lo, float& hi) {
    asm("mov.b64 {%0,%1},%2;" : "=f"(lo), "=f"(hi) : "l"(v));
}
__device__ __forceinline__ void ffma2(u64& acc, u64 a, u64 b) {
    asm("fma.rn.f32x2 %0,%1,%2,%0;" : "+l"(acc) : "l"(a), "l"(b));
}
__device__ __forceinline__ unsigned sptr(const void* p) {
    return (unsigned)__cvta_generic_to_shared(p);
}
__device__ __forceinline__ void cpa16(unsigned d, const void* s, int bytes) {
    asm volatile("cp.async.ca.shared.global [%0],[%1],16,%2;" :: "r"(d), "l"(s), "r"(bytes));
}
__device__ __forceinline__ void cpa8(unsigned d, const void* s, int bytes) {
    asm volatile("cp.async.ca.shared.global [%0],[%1],8,%2;" :: "r"(d), "l"(s), "r"(bytes));
}
__device__ __forceinline__ void cpcommit() { asm volatile("cp.async.commit_group;"); }
__device__ __forceinline__ void cpwait0()  { asm volatile("cp.async.wait_group 0;" ::: "memory"); }

// ---------------- device scratch ----------------
__device__ float g_A[P*D];
__device__ float g_B[P*D];
__device__ float g_C2[P*D];
__device__ float g_acc[P*D];
__device__ float g_hg[P*D];
__device__ float g_z2a[P*D];
__device__ float g_uA[NU*D];
__device__ float g_uB[NU*D];
__device__ float g_uC[NU*D];
__device__ float g_uacc[NU*D];
__device__ float g_ue[NU*D];
__device__ float g_z2b[NU*D];
__device__ float g_hus[NHE*D];
__device__ float g_ucl[NUC*D];
__device__ float g_X1r[P*D], g_X1i[P*D], g_X2r[P*D], g_X2i[P*D];
__device__ float g_Tr[(size_t)P*CW], g_Ti[(size_t)P*CW];
__device__ float g_Gr[P*D], g_Gi[P*D];
__device__ float g_fr[P*D], g_fi[P*D];
__device__ float g_fp[P*D];
__device__ float g_part[(size_t)8*MPAD*128];
__device__ float g_rp[(size_t)NT*MPAD];
__device__ float g_cp[(size_t)NT*MPAD];
__device__ float g_lr[NU], g_lc[NU], g_dg[NU];
__device__ float g_psum[8*NU];
__device__ float g_tabc[D*D], g_tabs[D*D];
__device__ float g_CrP[CW*D], g_CiP[CW*D];
__device__ float g_br[D], g_bi[D];
__device__ float g_fu[D];
__device__ float g_loss;

// =====================================================================
// Fused InfoNCE: cp.async Z1 staging + f32x2 FMA + fused exp/reductions.
// sim = 5*Z1@Z2^T (K=128). grid (nt,nt), 256 thr, 128x128 tile.
// Thread (tx,ty) owns rows ty*8..+7, cols {tx*4..+3, 64+tx*4..+3}.
// =====================================================================
__global__ __launch_bounds__(256, 2)
void nce_fused_k(const float* __restrict__ Z1, const float* __restrict__ Z2,
                 int M, float* __restrict__ rowp, float* __restrict__ colp)
{
    __shared__ __align__(16) float As[2][128*ASTR];
    __shared__ __align__(16) float Bs[2][16*132];
    __shared__ __align__(16) float red[128][17];

    int bm = blockIdx.y * 128, bn = blockIdx.x * 128;
    int t = threadIdx.x, tx = t & 15, ty = t >> 4;

    int ar0 = (2 * t) >> 2,     ak0 = ((2 * t) & 3) * 4;
    int ar1 = (2 * t + 1) >> 2, ak1 = ((2 * t + 1) & 3) * 4;
    int agm0 = bm + ar0, agm1 = bm + ar1;

    u64 acc2[8][4];
    #pragma unroll
    for (int i = 0; i < 8; i++)
        #pragma unroll
        for (int j = 0; j < 4; j++) acc2[i][j] = 0ULL;

    float4 rb[2];

    // prologue: stage 0
    {
        int b0 = (agm0 < M) ? 16 : 0;
        cpa16(sptr(&As[0][ar0 * ASTR + ak0]), b0 ? &Z1[(size_t)agm0 * 128 + ak0] : Z1, b0);
        int b1 = (agm1 < M) ? 16 : 0;
        cpa16(sptr(&As[0][ar1 * ASTR + ak1]), b1 ? &Z1[(size_t)agm1 * 128 + ak1] : Z1, b1);
        cpcommit();
        #pragma unroll
        for (int i = 0; i < 2; i++) {
            int f = t + i * 256, row = f >> 2, c4 = (f & 3) * 4;
            int gn = bn + row;
            rb[i] = (gn < M) ? *(const float4*)&Z2[(size_t)gn * 128 + c4]
                             : make_float4(0.f, 0.f, 0.f, 0.f);
        }
        #pragma unroll
        for (int i = 0; i < 2; i++) {
            int f = t + i * 256, row = f >> 2, c4 = (f & 3) * 4;
            Bs[0][(c4 + 0) * 132 + row] = rb[i].x;
            Bs[0][(c4 + 1) * 132 + row] = rb[i].y;
            Bs[0][(c4 + 2) * 132 + row] = rb[i].z;
            Bs[0][(c4 + 3) * 132 + row] = rb[i].w;
        }
        cpwait0();
        __syncthreads();
    }

    #pragma unroll 1
    for (int kt = 0; kt < 8; kt++) {
        int cur = kt & 1, nb = 1 - cur;
        if (kt < 7) {
            int k0 = (kt + 1) * 16;
            int b0 = (agm0 < M) ? 16 : 0;
            cpa16(sptr(&As[nb][ar0 * ASTR + ak0]), b0 ? &Z1[(size_t)agm0 * 128 + k0 + ak0] : Z1, b0);
            int b1 = (agm1 < M) ? 16 : 0;
            cpa16(sptr(&As[nb][ar1 * ASTR + ak1]), b1 ? &Z1[(size_t)agm1 * 128 + k0 + ak1] : Z1, b1);
            cpcommit();
            #pragma unroll
            for (int i = 0; i < 2; i++) {
                int f = t + i * 256, row = f >> 2, c4 = (f & 3) * 4;
                int gn = bn + row;
                rb[i] = (gn < M) ? *(const float4*)&Z2[(size_t)gn * 128 + k0 + c4]
                                 : make_float4(0.f, 0.f, 0.f, 0.f);
            }
        }
        const float* as = As[cur];
        const float* bs = Bs[cur];
        #pragma unroll
        for (int k2 = 0; k2 < 8; k2++) {
            u64 a2[8];
            #pragma unroll
            for (int i = 0; i < 8; i++)
                a2[i] = *(const u64*)&as[(ty * 8 + i) * ASTR + k2 * 2];
            const float* r0 = &bs[(k2 * 2) * 132];
            const float* r1 = &bs[(k2 * 2 + 1) * 132];
            double2 p;
            u64 bl[4], bh[4];
            p = *(const double2*)&r0[tx * 4];      bl[0] = __double_as_longlong(p.x); bl[1] = __double_as_longlong(p.y);
            p = *(const double2*)&r0[64 + tx * 4]; bl[2] = __double_as_longlong(p.x); bl[3] = __double_as_longlong(p.y);
            p = *(const double2*)&r1[tx * 4];      bh[0] = __double_as_longlong(p.x); bh[1] = __double_as_longlong(p.y);
            p = *(const double2*)&r1[64 + tx * 4]; bh[2] = __double_as_longlong(p.x); bh[3] = __double_as_longlong(p.y);
            #pragma unroll
            for (int i = 0; i < 8; i++) {
                float al, ah; unpack2(a2[i], al, ah);
                u64 aL = pack2(al, al), aH = pack2(ah, ah);
                ffma2(acc2[i][0], aL, bl[0]); ffma2(acc2[i][1], aL, bl[1]);
                ffma2(acc2[i][2], aL, bl[2]); ffma2(acc2[i][3], aL, bl[3]);
                ffma2(acc2[i][0], aH, bh[0]); ffma2(acc2[i][1], aH, bh[1]);
                ffma2(acc2[i][2], aH, bh[2]); ffma2(acc2[i][3], aH, bh[3]);
            }
        }
        if (kt < 7) {
            #pragma unroll
            for (int i = 0; i < 2; i++) {
                int f = t + i * 256, row = f >> 2, c4 = (f & 3) * 4;
                Bs[nb][(c4 + 0) * 132 + row] = rb[i].x;
                Bs[nb][(c4 + 1) * 132 + row] = rb[i].y;
                Bs[nb][(c4 + 2) * 132 + row] = rb[i].z;
                Bs[nb][(c4 + 3) * 132 + row] = rb[i].w;
            }
            cpwait0();
            __syncthreads();
        }
    }

    // epilogue: exp + row/col partial sums
    float rs[8], csv[8];
    #pragma unroll
    for (int i = 0; i < 8; i++) { rs[i] = 0.f; csv[i] = 0.f; }
    #pragma unroll
    for (int i = 0; i < 8; i++) {
        int gm = bm + ty * 8 + i;
        #pragma unroll
        for (int jp = 0; jp < 4; jp++) {
            float c0, c1;
            unpack2(acc2[i][jp], c0, c1);
            int bn_loc = (jp < 2) ? tx * 4 + jp * 2 : 64 + tx * 4 + (jp - 2) * 2;
            int gn0 = bn + bn_loc, gn1 = gn0 + 1;
            float e0 = (gm < M && gn0 < M) ? __expf(c0 * 5.f - 5.f) : 0.f;
            float e1 = (gm < M && gn1 < M) ? __expf(c1 * 5.f - 5.f) : 0.f;
            rs[i] += e0 + e1;
            int q = (jp < 2) ? jp * 2 : 4 + (jp - 2) * 2;
            csv[q] += e0; csv[q + 1] += e1;
        }
    }
    __syncthreads();
    #pragma unroll
    for (int i = 0; i < 8; i++) red[ty * 8 + i][tx] = rs[i];
    __syncthreads();
    if (t < 128) {
        float s = 0.f;
        #pragma unroll
        for (int q = 0; q < 16; q++) s += red[t][q];
        rowp[(size_t)blockIdx.x * MPAD + bm + t] = s;
    }
    __syncthreads();
    #pragma unroll
    for (int q = 0; q < 4; q++) {
        red[tx * 4 + q][ty]      = csv[q];
        red[64 + tx * 4 + q][ty] = csv[4 + q];
    }
    __syncthreads();
    if (t < 128) {
        float s = 0.f;
        #pragma unroll
        for (int q = 0; q < 16; q++) s += red[t][q];
        colp[(size_t)blockIdx.y * MPAD + bn + t] = s;
    }
}

// =====================================================================
// Split-K GEMM N=128, cp.async 2-stage + f32x2.
// A staging: 16B chunks when K%4==0 (src 16B-aligned per row),
// else 8B chunks (K even; src 8B-aligned). grid (S, mtiles).
// =====================================================================
__global__ __launch_bounds__(256, 2)
void gemm_n128_k(const float* __restrict__ A, const float* __restrict__ B,
                 float* __restrict__ Cp, int M, int K, int Kc)
{
    __shared__ __align__(16) float As[2][128*ASTR];
    __shared__ __align__(16) float Bs[2][16*132];

    int s = blockIdx.x, bm = blockIdx.y * 128;
    int kb = s * Kc;
    int ke = min(K, kb + Kc);
    int nt = (ke > kb) ? (ke - kb + 15) / 16 : 0;
    int t = threadIdx.x, tx = t & 15, ty = t >> 4;
    bool a16 = ((K & 3) == 0);

    int ar0 = (2 * t) >> 2,     ak0 = ((2 * t) & 3) * 4;
    int ar1 = (2 * t + 1) >> 2, ak1 = ((2 * t + 1) & 3) * 4;
    int agm0 = bm + ar0, agm1 = bm + ar1;
    int bk0 = (2 * t) >> 5,     bn0 = ((2 * t) & 31) * 4;
    int bk1 = (2 * t + 1) >> 5, bn1 = ((2 * t + 1) & 31) * 4;

    u64 acc2[8][4];
    #pragma unroll
    for (int i = 0; i < 8; i++)
        #pragma unroll
        for (int j = 0; j < 4; j++) acc2[i][j] = 0ULL;

    if (nt > 0) {
        int k0 = kb, klen = min(16, ke - k0);
        int b;
        if (a16) {
            b = (agm0 < M) ? min(max(klen - ak0, 0), 4) * 4 : 0;
            cpa16(sptr(&As[0][ar0 * ASTR + ak0]), b ? &A[(size_t)agm0 * K + k0 + ak0] : A, b);
            b = (agm1 < M) ? min(max(klen - ak1, 0), 4) * 4 : 0;
            cpa16(sptr(&As[0][ar1 * ASTR + ak1]), b ? &A[(size_t)agm1 * K + k0 + ak1] : A, b);
        } else {
            #pragma unroll
            for (int i = 0; i < 4; i++) {
                int c = 4 * t + i;
                int row = c >> 3, ko = (c & 7) * 2;
                int gm = bm + row;
                int bb = (gm < M) ? min(max(klen - ko, 0), 2) * 4 : 0;
                cpa8(sptr(&As[0][row * ASTR + ko]), bb ? &A[(size_t)gm * K + k0 + ko] : A, bb);
            }
        }
        b = (bk0 < klen) ? 16 : 0;
        cpa16(sptr(&Bs[0][bk0 * 132 + bn0]), b ? &B[(size_t)(k0 + bk0) * 128 + bn0] : B, b);
        b = (bk1 < klen) ? 16 : 0;
        cpa16(sptr(&Bs[0][bk1 * 132 + bn1]), b ? &B[(size_t)(k0 + bk1) * 128 + bn1] : B, b);
        cpcommit();
        cpwait0();
        __syncthreads();
    }

    for (int kt = 0; kt < nt; kt++) {
        int cur = kt & 1, nb = 1 - cur;
        if (kt + 1 < nt) {
            int k0 = kb + (kt + 1) * 16, klen = min(16, ke - k0);
            int b;
            if (a16) {
                b = (agm0 < M) ? min(max(klen - ak0, 0), 4) * 4 : 0;
                cpa16(sptr(&As[nb][ar0 * ASTR + ak0]), b ? &A[(size_t)agm0 * K + k0 + ak0] : A, b);
                b = (agm1 < M) ? min(max(klen - ak1, 0), 4) * 4 : 0;
                cpa16(sptr(&As[nb][ar1 * ASTR + ak1]), b ? &A[(size_t)agm1 * K + k0 + ak1] : A, b);
            } else {
                #pragma unroll
                for (int i = 0; i < 4; i++) {
                    int c = 4 * t + i;
                    int row = c >> 3, ko = (c & 7) * 2;
                    int gm = bm + row;
                    int bb = (gm < M) ? min(max(klen - ko, 0), 2) * 4 : 0;
                    cpa8(sptr(&As[nb][row * ASTR + ko]), bb ? &A[(size_t)gm * K + k0 + ko] : A, bb);
                }
            }
            b = (bk0 < klen) ? 16 : 0;
            cpa16(sptr(&Bs[nb][bk0 * 132 + bn0]), b ? &B[(size_t)(k0 + bk0) * 128 + bn0] : B, b);
            b = (bk1 < klen) ? 16 : 0;
            cpa16(sptr(&Bs[nb][bk1 * 132 + bn1]), b ? &B[(size_t)(k0 + bk1) * 128 + bn1] : B, b);
            cpcommit();
        }
        const float* as = As[cur];
        const float* bs = Bs[cur];
        #pragma unroll
        for (int k2 = 0; k2 < 8; k2++) {
            u64 a2[8];
            #pragma unroll
            for (int i = 0; i < 8; i++)
                a2[i] = *(const u64*)&as[(ty * 8 + i) * ASTR + k2 * 2];
            const float* r0 = &bs[(k2 * 2) * 132];
            const float* r1 = &bs[(k2 * 2 + 1) * 132];
            double2 p;
            u64 bl[4], bh[4];
            p = *(const double2*)&r0[tx * 4];      bl[0] = __double_as_longlong(p.x); bl[1] = __double_as_longlong(p.y);
            p = *(const double2*)&r0[64 + tx * 4]; bl[2] = __double_as_longlong(p.x); bl[3] = __double_as_longlong(p.y);
            p = *(const double2*)&r1[tx * 4];      bh[0] = __double_as_longlong(p.x); bh[1] = __double_as_longlong(p.y);
            p = *(const double2*)&r1[64 + tx * 4]; bh[2] = __double_as_longlong(p.x); bh[3] = __double_as_longlong(p.y);
            #pragma unroll
            for (int i = 0; i < 8; i++) {
                float al, ah; unpack2(a2[i], al, ah);
                u64 aL = pack2(al, al), aH = pack2(ah, ah);
                ffma2(acc2[i][0], aL, bl[0]); ffma2(acc2[i][1], aL, bl[1]);
                ffma2(acc2[i][2], aL, bl[2]); ffma2(acc2[i][3], aL, bl[3]);
                ffma2(acc2[i][0], aH, bh[0]); ffma2(acc2[i][1], aH, bh[1]);
                ffma2(acc2[i][2], aH, bh[2]); ffma2(acc2[i][3], aH, bh[3]);
            }
        }
        if (kt + 1 < nt) {
            cpwait0();
            __syncthreads();
        }
    }

    size_t base = (size_t)s * ((size_t)MPAD * 128);
    #pragma unroll
    for (int i = 0; i < 8; i++) {
        int gm = bm + ty * 8 + i;
        if (gm >= M) continue;
        float c[8];
        #pragma unroll
        for (int jp = 0; jp < 4; jp++) unpack2(acc2[i][jp], c[jp * 2], c[jp * 2 + 1]);
        *(float4*)&Cp[base + (size_t)gm * 128 + tx * 4]      = make_float4(c[0], c[1], c[2], c[3]);
        *(float4*)&Cp[base + (size_t)gm * 128 + 64 + tx * 4] = make_float4(c[4], c[5], c[6], c[7]);
    }
}

__global__ void comb_n128_k(const float* __restrict__ Cp, int S,
                            float* __restrict__ C, int M, float alpha, int accum)
{
    int i = blockIdx.x * 256 + threadIdx.x;
    if (i >= M * 128) return;
    float s = 0.f;
    for (int q = 0; q < S; q++) s += Cp[(size_t)q * ((size_t)MPAD * 128) + i];
    float v = alpha * s;
    C[i] = accum ? C[i] + v : v;
}

__global__ void lse_comb_k(const float* __restrict__ pp, int ntiles,
                           float* __restrict__ lse, int M)
{
    int r = blockIdx.x * 256 + threadIdx.x;
    if (r >= M) return;
    float s = 0.f;
    for (int q = 0; q < ntiles; q++) s += pp[(size_t)q * MPAD + r];
    lse[r] = 5.f + logf(s);
}

__global__ void diag_k(const float* __restrict__ Z1, const float* __restrict__ Z2,
                       int M, float* __restrict__ dg)
{
    int gt = blockIdx.x * blockDim.x + threadIdx.x;
    int r = gt >> 5, lane = gt & 31;
    if (r >= M) return;
    const float* a = Z1 + (size_t)r * 128;
    const float* b = Z2 + (size_t)r * 128;
    float s = 0.f;
    #pragma unroll
    for (int d = lane; d < 128; d += 32) s += a[d] * b[d];
    #pragma unroll
    for (int off = 16; off; off >>= 1) s += __shfl_down_sync(0xffffffffu, s, off);
    if (lane == 0) dg[r] = 5.f * s;
}

// =====================================================================
// generic FFMA SGEMM (small cases: K=51 hconv, 42x42 NCE)
// =====================================================================
__global__ void sgemm_kernel(const float* __restrict__ A, const float* __restrict__ B,
                             float* __restrict__ C, int M, int N, int K,
                             float alpha, int transB, int accum)
{
    __shared__ __align__(16) float As[16][68];
    __shared__ __align__(16) float Bs[16][68];
    int bm = blockIdx.y * 64, bn = blockIdx.x * 64;
    int t  = threadIdx.x;
    int ty = t >> 4, tx = t & 15;
    float acc[4][4];
    #pragma unroll
    for (int i = 0; i < 4; i++)
        #pragma unroll
        for (int j = 0; j < 4; j++) acc[i][j] = 0.f;

    for (int k0 = 0; k0 < K; k0 += 16) {
        #pragma unroll
        for (int i = 0; i < 4; i++) {
            int e  = t + i * 256;
            int mm = e >> 4, kk = e & 15;
            int gm = bm + mm, gk = k0 + kk;
            As[kk][mm] = (gm < M && gk < K) ? A[(size_t)gm * K + gk] : 0.f;
        }
        if (!transB) {
            #pragma unroll
            for (int i = 0; i < 4; i++) {
                int e  = t + i * 256;
                int kk = e >> 6, nn = e & 63;
                int gk = k0 + kk, gn = bn + nn;
                Bs[kk][nn] = (gk < K && gn < N) ? B[(size_t)gk * N + gn] : 0.f;
            }
        } else {
            #pragma unroll
            for (int i = 0; i < 4; i++) {
                int e  = t + i * 256;
                int nn = e >> 4, kk = e & 15;
                int gn = bn + nn, gk = k0 + kk;
                Bs[kk][nn] = (gn < N && gk < K) ? B[(size_t)gn * K + gk] : 0.f;
            }
        }
        __syncthreads();
        #pragma unroll
        for (int kk = 0; kk < 16; kk++) {
            float4 av = *(const float4*)&As[kk][ty * 4];
            float4 bv = *(const float4*)&Bs[kk][tx * 4];
            float a4[4] = {av.x, av.y, av.z, av.w};
            float b4[4] = {bv.x, bv.y, bv.z, bv.w};
            #pragma unroll
            for (int i = 0; i < 4; i++)
                #pragma unroll
                for (int j = 0; j < 4; j++) acc[i][j] += a4[i] * b4[j];
        }
        __syncthreads();
    }
    #pragma unroll
    for (int i = 0; i < 4; i++) {
        int gm = bm + ty * 4 + i;
        if (gm >= M) continue;
        #pragma unroll
        for (int j = 0; j < 4; j++) {
            int gn = bn + tx * 4 + j;
            if (gn >= N) continue;
            size_t idx = (size_t)gm * N + gn;
            float v = alpha * acc[i][j];
            C[idx] = accum ? (C[idx] + v) : v;
        }
    }
}

// ---- tall-skinny: C(NHE x 128) = A(NHE x K) @ B(K x 128) ----
__global__ void skinny_mm_k(const float* __restrict__ A, const float* __restrict__ B,
                            float* __restrict__ C, int K)
{
    int m = blockIdx.x;
    int t = threadIdx.x;
    int n = t & 127;
    int q = t >> 7;
    const float* a = A + (size_t)m * K;
    float s0 = 0.f, s1 = 0.f;
    for (int k = q; k < K; k += 8) {
        s0 += a[k] * B[(size_t)k * 128 + n];
        int k2 = k + 4;
        if (k2 < K) s1 += a[k2] * B[(size_t)k2 * 128 + n];
    }
    __shared__ float sh[3][128];
    float s = s0 + s1;
    if (q) sh[q - 1][n] = s;
    __syncthreads();
    if (q == 0) C[(size_t)m * 128 + n] = s + sh[0][n] + sh[1][n] + sh[2][n];
}

// ---------------- elementwise ----------------
__global__ void copy_k(float* d, const float* s, int n) {
    int i = blockIdx.x * blockDim.x + threadIdx.x;
    if (i < n) d[i] = s[i];
}
__global__ void add_k(float* d, const float* s, int n) {
    int i = blockIdx.x * blockDim.x + threadIdx.x;
    if (i < n) d[i] += s[i];
}
__global__ void gate_k(const float* __restrict__ w, const float* __restrict__ tm,
                       const float* __restrict__ b, float* __restrict__ out, int n) {
    int i = blockIdx.x * blockDim.x + threadIdx.x;
    if (i >= n) return;
    float z = tm[i] + b[i & 127];
    out[i] = w[i] / (1.f + expf(-z));
}
__global__ void kan_gate_k(const float* __restrict__ G, const float* __restrict__ bias,
                           const float* __restrict__ Xa, const float* __restrict__ Xb,
                           float* __restrict__ f, int n) {
    int i = blockIdx.x * blockDim.x + threadIdx.x;
    if (i >= n) return;
    float g = 1.f / (1.f + expf(-(G[i] + bias[i & 127])));
    f[i] = g * Xa[i] + (1.f - g) * Xb[i];
}
__global__ void buildT_k(const float* __restrict__ Xa, const float* __restrict__ Xb,
                         float* __restrict__ T, int n) {
    int i = blockIdx.x * blockDim.x + threadIdx.x;
    if (i >= n) return;
    int row = i >> 7, c = i & 127;
    float x  = tanhf(Xa[i]);
    float t2 = 2.f * x * x - 1.f;
    float t3 = 2.f * x * t2 - x;
    float* p = T + (size_t)row * CW + c * 3;
    p[0] = x; p[1] = t2; p[2] = t3;
    x  = tanhf(Xb[i]);
    t2 = 2.f * x * x - 1.f;
    t3 = 2.f * x * t2 - x;
    p = T + (size_t)row * CW + 384 + c * 3;
    p[0] = x; p[1] = t2; p[2] = t3;
}

// ---------------- L2 normalize ----------------
__global__ void l2norm_k(const float* __restrict__ x, float* __restrict__ y) {
    int r = blockIdx.x, t = threadIdx.x;
    float v = x[(size_t)r * 128 + t];
    __shared__ float sh[128];
    sh[t] = v * v; __syncthreads();
    for (int st = 64; st; st >>= 1) { if (t < st) sh[t] += sh[t + st]; __syncthreads(); }
    y[(size_t)r * 128 + t] = v / fmaxf(sqrtf(sh[0]), 1e-12f);
}
__global__ void addnorm_k(const float* __restrict__ x, const float* __restrict__ ns,
                          float* __restrict__ y) {
    int r = blockIdx.x, t = threadIdx.x;
    float v = x[(size_t)r * 128 + t] + ns[(size_t)r * 128 + t];
    __shared__ float sh[128];
    sh[t] = v * v; __syncthreads();
    for (int st = 64; st; st >>= 1) { if (t < st) sh[t] += sh[t + st]; __syncthreads(); }
    y[(size_t)r * 128 + t] = v / fmaxf(sqrtf(sh[0]), 1e-12f);
}

// ---------------- small InfoNCE path (NUC only) ----------------
__global__ void row_lse_k(const float* __restrict__ S, float* lse, float* diag, int M) {
    int r = blockIdx.x, t = threadIdx.x;
    const float* row = S + (size_t)r * M;
    float s = 0.f;
    for (int j = t; j < M; j += 128) s += expf(row[j] - 5.0f);
    __shared__ float sh[128];
    sh[t] = s; __syncthreads();
    for (int st = 64; st; st >>= 1) { if (t < st) sh[t] += sh[t + st]; __syncthreads(); }
    if (t == 0) { lse[r] = 5.0f + logf(sh[0]); diag[r] = row[r]; }
}
__global__ void col_part_k(const float* __restrict__ S, int M, int splits) {
    int col = blockIdx.x * 256 + threadIdx.x;
    if (col >= M) return;
    int sp = blockIdx.y;
    long r0 = (long)M * sp / splits, r1 = (long)M * (sp + 1) / splits;
    float s = 0.f;
    for (long r = r0; r < r1; r++) s += expf(S[(size_t)r * M + col] - 5.0f);
    g_psum[sp * NU + col] = s;
}
__global__ void col_comb_k(float* lsec, int M, int splits) {
    int col = blockIdx.x * 256 + threadIdx.x;
    if (col >= M) return;
    float s = 0.f;
    for (int sp = 0; sp < splits; sp++) s += g_psum[sp * NU + col];
    lsec[col] = 5.0f + logf(s);
}
__global__ void nce_accum_k(const float* lr, const float* lc, const float* dg, int M) {
    __shared__ float sh[256];
    int t = threadIdx.x;
    float a = 0.f;
    for (int i = t; i < M; i += 256) a += (lr[i] - dg[i]) + (lc[i] - dg[i]);
    sh[t] = a; __syncthreads();
    for (int st = 128; st; st >>= 1) { if (t < st) sh[t] += sh[t + st]; __syncthreads(); }
    if (t == 0) g_loss += 0.5f * sh[0] / (float)M;
}

// ---------------- setup ----------------
__global__ void setup_tab_k() {
    int i = blockIdx.x * blockDim.x + threadIdx.x;
    if (i >= D * D) return;
    int a = i >> 7, b = i & 127;
    float ang = 6.28318530717958647692f * (float)((a * b) & 127) / 128.f;
    g_tabc[i] = cosf(ang);
    g_tabs[i] = sinf(ang);
}
__global__ void pack_cheb_k(const float* __restrict__ cr, const float* __restrict__ ci) {
    int i = blockIdx.x * blockDim.x + threadIdx.x;
    if (i >= CW * D) return;
    int r = i >> 7, o = i & 127;
    int rr = r % 384;
    int ii = rr / 3, k = rr % 3 + 1;
    g_CrP[i] = cr[((size_t)ii * 128 + o) * 4 + k];
    g_CiP[i] = ci[((size_t)ii * 128 + o) * 4 + k];
}
__global__ void bias_k(const float* __restrict__ cr, const float* __restrict__ ci) {
    int o = threadIdx.x;
    float s1 = 0.f, s2 = 0.f;
    for (int ii = 0; ii < 128; ii++) {
        s1 += cr[((size_t)ii * 128 + o) * 4];
        s2 += ci[((size_t)ii * 128 + o) * 4];
    }
    g_br[o] = 2.f * s1;
    g_bi[o] = 2.f * s2;
    if (o == 0) g_loss = 0.f;
}

// ---------------- finals ----------------
__global__ void finalu_k(const int* __restrict__ uui, const int* __restrict__ ucol) {
    int d = threadIdx.x;
    g_fu[d] = g_ue[(size_t)(*uui) * 128 + d] + g_hus[(size_t)(*ucol) * 128 + d];
}
__global__ void outvec_k(const float* __restrict__ fp, float* __restrict__ out) {
    int gt = blockIdx.x * blockDim.x + threadIdx.x;
    int w = gt >> 5, lane = gt & 31;
    if (w >= P) return;
    const float* row = fp + (size_t)w * 128;
    float s = 0.f;
    #pragma unroll
    for (int d = lane; d < 128; d += 32) s += row[d] * g_fu[d];
    #pragma unroll
    for (int off = 16; off; off >>= 1) s += __shfl_down_sync(0xffffffffu, s, off);
    if (lane == 0) out[w] = s;
}
__global__ void final_k(float* __restrict__ dout, const int* __restrict__ target) {
    __shared__ float sm[1024], ss[1024];
    int t = threadIdx.x;
    float m = -1e30f, s = 0.f;
    for (int j = t; j < P; j += 1024) {
        float x = dout[1 + j];
        float nm = fmaxf(m, x);
        s = s * expf(m - nm) + expf(x - nm);
        m = nm;
    }
    sm[t] = m; ss[t] = s; __syncthreads();
    for (int st = 512; st; st >>= 1) {
        if (t < st) {
            float m2 = sm[t + st], s2 = ss[t + st];
            float nm = fmaxf(sm[t], m2);
            ss[t] = ss[t] * expf(sm[t] - nm) + s2 * expf(m2 - nm);
            sm[t] = nm;
        }
        __syncthreads();
    }
    if (t == 0) {
        float lse = sm[0] + logf(ss[0]);
        dout[0] = (lse - dout[1 + (*target)]) + g_loss;
    }
}

// ---------------- host orchestration ----------------
static inline dim3 ew(int n) { return dim3((n + 255) / 256); }

#define GSYM(p, s) do { void* _q = nullptr; cudaGetSymbolAddress(&_q, s); p = (float*)_q; } while (0)

static float *s_part;

static void gemm128(const float* A, const float* B, float* C, int M, int K, int S,
                    float alpha, bool accum)
{
    int Kc = (((K + S - 1) / S) + 15) & ~15;
    dim3 g(S, (M + 127) / 128);
    gemm_n128_k<<<g, 256>>>(A, B, s_part, M, K, Kc);
    comb_n128_k<<<ew(M * 128), 256>>>(s_part, S, C, M, alpha, accum ? 1 : 0);
}

static void run_nce(const float* Z1, const float* Z2, int M,
                    float* rp, float* cp, float* lr, float* lc, float* dg)
{
    int nt = (M + 127) / 128;
    dim3 g(nt, nt);
    nce_fused_k<<<g, 256>>>(Z1, Z2, M, rp, cp);
    lse_comb_k<<<ew(M), 256>>>(rp, nt, lr, M);
    lse_comb_k<<<ew(M), 256>>>(cp, nt, lc, M);
    diag_k<<<(M * 32 + 255) / 256, 256>>>(Z1, Z2, M, dg);
    nce_accum_k<<<1, 256>>>(lr, lc, dg, M);
}

extern "C" void kernel_launch(void* const* d_in, const int* in_sizes, int n_in,
                              void* d_out, int out_size)
{
    const float* poi_w    = (const float*)d_in[0];
    const float* ui_w     = (const float*)d_in[1];
    const float* w_gc     = (const float*)d_in[2];
    const float* b_gc     = (const float*)d_in[3];
    const float* w_gU     = (const float*)d_in[4];
    const float* b_gU     = (const float*)d_in[5];
    const float* cheb_r   = (const float*)d_in[6];
    const float* cheb_i   = (const float*)d_in[7];
    const float* HG_pu    = (const float*)d_in[8];
    const float* HG_up    = (const float*)d_in[9];
    const float* U_I      = (const float*)d_in[10];
    const float* noise1   = (const float*)d_in[11];
    const float* noise2   = (const float*)d_in[12];
    const int*   target   = (const int*)d_in[13];
    const int*   user_col = (const int*)d_in[14];
    const int*   user_ui  = (const int*)d_in[15];
    float* out = (float*)d_out;

    float *A, *B, *C2, *acc, *hg, *z2a, *uA, *uB, *uC, *uacc, *ue, *z2b;
    float *hus, *ucl, *X1r, *X1i, *X2r, *X2i, *Tr, *Ti, *Gr, *Gi, *fr, *fi, *fp;
    float *lr, *lc, *dg, *tabc, *tabs, *CrP, *CiP, *br, *bi, *rp, *cp;
    GSYM(A, g_A); GSYM(B, g_B); GSYM(C2, g_C2); GSYM(acc, g_acc);
    GSYM(hg, g_hg); GSYM(z2a, g_z2a);
    GSYM(uA, g_uA); GSYM(uB, g_uB); GSYM(uC, g_uC); GSYM(uacc, g_uacc);
    GSYM(ue, g_ue); GSYM(z2b, g_z2b);
    GSYM(hus, g_hus); GSYM(ucl, g_ucl);
    GSYM(X1r, g_X1r); GSYM(X1i, g_X1i); GSYM(X2r, g_X2r); GSYM(X2i, g_X2i);
    GSYM(Tr, g_Tr); GSYM(Ti, g_Ti); GSYM(Gr, g_Gr); GSYM(Gi, g_Gi);
    GSYM(fr, g_fr); GSYM(fi, g_fi); GSYM(fp, g_fp);
    GSYM(lr, g_lr); GSYM(lc, g_lc); GSYM(dg, g_dg);
    GSYM(tabc, g_tabc); GSYM(tabs, g_tabs); GSYM(CrP, g_CrP); GSYM(CiP, g_CiP);
    GSYM(br, g_br); GSYM(bi, g_bi); GSYM(rp, g_rp); GSYM(cp, g_cp);
    GSYM(s_part, g_part);

    // setup (also zeroes loss accumulator)
    setup_tab_k<<<ew(D * D), 256>>>();
    pack_cheb_k<<<ew(CW * D), 256>>>(cheb_r, cheb_i);
    bias_k<<<1, 128>>>(cheb_r, cheb_i);

    // gated embeddings
    gemm128(poi_w, w_gc, B, P, 128, 4, 1.f, false);
    gate_k<<<ew(P * D), 256>>>(poi_w, B, b_gc, A, P * D);
    gemm128(ui_w, w_gU, uB, NU, 128, 4, 1.f, false);
    gate_k<<<ew(NU * D), 256>>>(ui_w, uB, b_gU, uA, NU * D);

    // hconv (2 layers) -> hg
    copy_k<<<ew(P * D), 256>>>(acc, A, P * D);
    skinny_mm_k<<<NHE, 512>>>(HG_pu, A, hus, P);
    { dim3 g(2, 128); sgemm_kernel<<<g, 256>>>(HG_up, hus, B, P, 128, NHE, 1.f, 0, 0); }
    add_k<<<ew(P * D), 256>>>(acc, B, P * D);
    skinny_mm_k<<<NHE, 512>>>(HG_pu, B, hus, P);
    { dim3 g(2, 128); sgemm_kernel<<<g, 256>>>(HG_up, hus, C2, P, 128, NHE, 1.f, 0, 0); }
    add_k<<<ew(P * D), 256>>>(acc, C2, P * D);
    l2norm_k<<<P, 128>>>(acc, hg);
    addnorm_k<<<P, 128>>>(hg, noise1, z2a);

    // level_loss = info_nce(hg, hg+noise1)
    run_nce(hg, z2a, P, rp, cp, lr, lc, dg);

    // hg_users
    skinny_mm_k<<<NHE, 512>>>(HG_pu, hg, hus, P);

    // gconv (2 layers) -> ue
    copy_k<<<ew(NU * D), 256>>>(uacc, uA, NU * D);
    gemm128(U_I, uA, uB, NU, NU, 8, 1.f, false);
    add_k<<<ew(NU * D), 256>>>(uacc, uB, NU * D);
    gemm128(U_I, uB, uC, NU, NU, 8, 1.f, false);
    add_k<<<ew(NU * D), 256>>>(uacc, uC, NU * D);
    l2norm_k<<<NU, 128>>>(uacc, ue);
    addnorm_k<<<NU, 128>>>(ue, noise2, z2b);

    // level_loss1 = info_nce(ue, ue+noise2)
    run_nce(ue, z2b, NU, rp, cp, lr, lc, dg);

    const float* poi_e = ue + (size_t)NUC * D;

    // ssl_p = info_nce(hg, poi_e)
    run_nce(hg, poi_e, P, rp, cp, lr, lc, dg);

    // ssl = info_nce(ue[0:42], l2norm(hg_users[9:]))  (small path)
    l2norm_k<<<NUC, 128>>>(hus + 9 * D, ucl);
    { dim3 g(1, 1); sgemm_kernel<<<g, 256>>>(ue, ucl, s_part, NUC, NUC, 128, 5.f, 1, 0); }
    row_lse_k<<<NUC, 128>>>(s_part, lr, dg, NUC);
    { dim3 g(1, 1); col_part_k<<<g, 256>>>(s_part, NUC, 1); }
    col_comb_k<<<1, 256>>>(lc, NUC, 1);
    nce_accum_k<<<1, 256>>>(lr, lc, dg, NUC);

    // gated KAN: DFT -> cheby gate -> IDFT
    gemm128(hg, tabc, X1r, P, 128, 4,  1.f, false);
    gemm128(hg, tabs, X1i, P, 128, 4, -1.f, false);
    gemm128(poi_e, tabc, X2r, P, 128, 4,  1.f, false);
    gemm128(poi_e, tabs, X2i, P, 128, 4, -1.f, false);
    buildT_k<<<ew(P * D), 256>>>(X1r, X2r, Tr, P * D);
    buildT_k<<<ew(P * D), 256>>>(X1i, X2i, Ti, P * D);
    gemm128(Tr, CrP, Gr, P, CW, 4, 1.f, false);
    gemm128(Ti, CiP, Gi, P, CW, 4, 1.f, false);
    kan_gate_k<<<ew(P * D), 256>>>(Gr, br, X1r, X2r, fr, P * D);
    kan_gate_k<<<ew(P * D), 256>>>(Gi, bi, X1i, X2i, fi, P * D);
    gemm128(fr, tabc, fp, P, 128, 4,  1.f / 128.f, false);
    gemm128(fi, tabs, fp, P, 128, 4, -1.f / 128.f, true);

    // final user vector, logits, loss
    finalu_k<<<1, 128>>>(user_ui, user_col);
    outvec_k<<<(P * 32 + 255) / 256, 256>>>(fp, out + 1);
    final_k<<<1, 1024>>>(out, target);
}